// round 12
// baseline (speedup 1.0000x reference)
#include <cuda_runtime.h>
#include <math.h>
#include <stdint.h>

#define BB 2
#define NNPTS 4096
#define CF 64
#define KNN 32
#define NTOT (BB*NNPTS)

// ---------------- scratch (static __device__, no allocs) ----------------
__device__ float  g_K[(size_t)BB*NNPTS*NNPTS];   // 128 MB transport kernel
__device__ float  g_f0n[NTOT*CF];
__device__ float  g_f1n[NTOT*CF];
__device__ float  g_n0[NTOT];
__device__ float  g_n1[NTOT];
__device__ float4 g_pts0[NTOT];                  // packed (x,y,z,|p|^2) of pc0
__device__ float  g_colsum[NTOT];
__device__ float4 g_w4t[NTOT];                   // transposed (b, b*x, b*y, b*z)
__device__ float  g_otflow[NTOT*3];
__device__ int    g_idx[NTOT*KNN];
__device__ float  g_y2[NTOT*64];                 // x1 @ W2a (pre-gather transform)
__device__ float  g_y3[NTOT*128];                // x2 @ W3a

__device__ __forceinline__ float lrelu(float x){ return (x > 0.f) ? x : 0.1f*x; }

// ---------------- prep part 1: point norms + packed pts + colsum zero ----
__global__ __launch_bounds__(256)
void prep_norm_kernel(const float* __restrict__ pc0, const float* __restrict__ pc1)
{
    int i = blockIdx.x*blockDim.x + threadIdx.x;
    if (i >= 2*NTOT) return;
    int which = i / NTOT, row = i % NTOT;
    const float* pc = which ? pc1 : pc0;
    float x = pc[row*3+0], y = pc[row*3+1], z = pc[row*3+2];
    float n2 = x*x + y*y + z*z;
    if (which) g_n1[row] = n2;
    else {
        g_n0[row] = n2; g_colsum[row] = 0.f;
        g_pts0[row] = make_float4(x, y, z, n2);
    }
}

// ---------------- prep part 2: feature normalize -------------------------
__global__ __launch_bounds__(256)
void prep_feat_kernel(const float* __restrict__ f0, const float* __restrict__ f1)
{
    int w    = (blockIdx.x*blockDim.x + threadIdx.x) >> 5;
    int lane = threadIdx.x & 31;
    if (w >= 2*NTOT) return;
    int which = w / NTOT;
    int row   = w % NTOT;
    const float* f = which ? f1 : f0;
    float v0 = f[row*CF + lane];
    float v1 = f[row*CF + 32 + lane];
    float ss = v0*v0 + v1*v1;
    #pragma unroll
    for (int o = 16; o > 0; o >>= 1) ss += __shfl_xor_sync(0xffffffffu, ss, o);
    float inv = rsqrtf(ss + 1e-8f);
    float* out = which ? g_f1n : g_f0n;
    out[row*CF + lane]      = v0*inv;
    out[row*CF + 32 + lane] = v1*inv;
}

// ---------------- KNN: radix-select 32 smallest sqdists per row ----------
__global__ __launch_bounds__(256)
void knn_kernel()
{
    int n = blockIdx.x; int b = n / NNPTS;
    const float4* pts = g_pts0 + b*NNPTS;
    int tid = threadIdx.x;
    int lane = tid & 31;
    float4 q = g_pts0[n];
    unsigned key[16];
    #pragma unroll
    for (int i = 0; i < 16; i++) {
        float4 p = pts[tid + i*256];
        float dot = fmaf(p.x, q.x, fmaf(p.y, q.y, p.z*q.z));
        float d = q.w + p.w - 2.0f*dot;
        unsigned u = __float_as_uint(d);
        u = (u & 0x80000000u) ? ~u : (u | 0x80000000u);
        key[i] = u;
    }
    __shared__ int hist[256];
    __shared__ unsigned s_prefix;
    __shared__ int s_krem, s_cl, s_ct;
    __shared__ int s_out[KNN];
    __shared__ int s_tie[64];
    if (tid == 0) { s_prefix = 0u; s_krem = KNN; s_cl = 0; s_ct = 0; }
    for (int r = 0; r < 4; r++) {
        int shift = 24 - 8*r;
        hist[tid] = 0;
        __syncthreads();
        unsigned pref = s_prefix;
        unsigned msk  = (r == 0) ? 0u : (0xFFFFFFFFu << (32 - 8*r));
        #pragma unroll
        for (int i = 0; i < 16; i++)
            if ((key[i] & msk) == (pref & msk))
                atomicAdd(&hist[(key[i] >> shift) & 255], 1);
        __syncthreads();
        if (tid < 32) {                    // warp-0 parallel scan of 256 bins
            int krem = s_krem;
            int loc[8]; int tot = 0;
            #pragma unroll
            for (int j = 0; j < 8; j++) { loc[j] = hist[tid*8 + j]; tot += loc[j]; }
            int incl = tot;
            #pragma unroll
            for (int o = 1; o < 32; o <<= 1) {
                int x = __shfl_up_sync(0xffffffffu, incl, o);
                if (lane >= o) incl += x;
            }
            int excl = incl - tot;
            if (excl < krem && krem <= incl) {
                int rem = krem - excl;
                int d = 0;
                #pragma unroll
                for (int j = 0; j < 7; j++) if (rem > loc[d]) { rem -= loc[d]; d++; }
                s_prefix = pref | ((unsigned)(tid*8 + d) << shift);
                s_krem = rem;
            }
        }
        __syncthreads();
    }
    unsigned pivot = s_prefix;
    #pragma unroll
    for (int i = 0; i < 16; i++) {
        unsigned u = key[i];
        if (u < pivot)       { int p = atomicAdd(&s_cl, 1); s_out[p] = tid + i*256; }
        else if (u == pivot) { int t = atomicAdd(&s_ct, 1); if (t < 64) s_tie[t] = tid + i*256; }
    }
    __syncthreads();
    if (tid == 0) {
        int cl = s_cl;
        int nt = (s_ct < 64) ? s_ct : 64;
        int need = KNN - cl;                 // ties filled by lowest index (jax tie-break)
        for (int s = 0; s < need; s++) {
            int best = 0x7FFFFFFF, bi = 0;
            for (int t = 0; t < nt; t++) if (s_tie[t] < best) { best = s_tie[t]; bi = t; }
            s_tie[bi] = 0x7FFFFFFF;
            s_out[cl + s] = best;
        }
    }
    __syncthreads();
    if (tid < KNN) g_idx[n*KNN + tid] = s_out[tid];
}

// ---------------- K tile kernel: 128x64 tiles, 8x4 register blocking -----
// 3 blocks/SM (6 warps/SMSP) for latency hiding; conflict-free LDS.128;
// __expf epilogue. Row split 4+4 (rb, rb+64); cols direct (cb..cb+3).
__global__ __launch_bounds__(256, 3)
void kmat_kernel(const float* __restrict__ pc0, const float* __restrict__ pc1,
                 const float* __restrict__ epsilon)
{
    extern __shared__ float sm[];
    float* As      = sm;               // 64*132 = 8448
    float* Bs      = sm + 8448;        // 64*68  = 4352
    float* P0      = sm + 12800;       // 3*128
    float* P1      = sm + 13184;       // 3*64
    float* N0s     = sm + 13376;       // 128
    float* N1s     = sm + 13504;       // 64
    float* colpart = sm + 13568;       // 64
    // total 13632 floats = 54528 bytes

    int bz = blockIdx.z;
    int row0 = blockIdx.y*128, col0 = blockIdx.x*64;
    int tid = threadIdx.x;

    {   // A fill: 2 threads per row (128 rows), k-major transpose
        int r = tid >> 1, q = tid & 1;
        const float* a = g_f0n + (size_t)(bz*NNPTS + row0 + r)*CF + q*32;
        #pragma unroll
        for (int i = 0; i < 8; i++) {
            float4 va = *(const float4*)(a + 4*i);
            int k = q*32 + 4*i;
            As[(k+0)*132 + r] = va.x; As[(k+1)*132 + r] = va.y;
            As[(k+2)*132 + r] = va.z; As[(k+3)*132 + r] = va.w;
        }
    }
    {   // B fill: 4 threads per row (64 rows), k-major transpose
        int r = tid >> 2, q = tid & 3;
        const float* b = g_f1n + (size_t)(bz*NNPTS + col0 + r)*CF + q*16;
        #pragma unroll
        for (int i = 0; i < 4; i++) {
            float4 vb = *(const float4*)(b + 4*i);
            int k = q*16 + 4*i;
            Bs[(k+0)*68 + r] = vb.x; Bs[(k+1)*68 + r] = vb.y;
            Bs[(k+2)*68 + r] = vb.z; Bs[(k+3)*68 + r] = vb.w;
        }
    }
    if (tid < 128) {
        int r = tid;
        #pragma unroll
        for (int d = 0; d < 3; d++) P0[d*128 + r] = pc0[(bz*NNPTS+row0+r)*3 + d];
        N0s[r] = g_n0[bz*NNPTS + row0 + r];
    } else if (tid < 192) {
        int r = tid - 128;
        #pragma unroll
        for (int d = 0; d < 3; d++) P1[d*64 + r] = pc1[(bz*NNPTS+col0+r)*3 + d];
        N1s[r] = g_n1[bz*NNPTS + col0 + r];
        colpart[r] = 0.f;
    }
    __syncthreads();

    int rb = (tid >> 4)*4, cb = (tid & 15)*4;
    float acc[8][4];
    #pragma unroll
    for (int i = 0; i < 8; i++)
        #pragma unroll
        for (int j = 0; j < 4; j++) acc[i][j] = 0.f;

    #pragma unroll 4
    for (int k = 0; k < 64; k++) {
        float4 a0 = *(const float4*)&As[k*132 + rb];
        float4 a1 = *(const float4*)&As[k*132 + rb + 64];
        float4 b0 = *(const float4*)&Bs[k*68 + cb];
        float ar[8] = {a0.x,a0.y,a0.z,a0.w,a1.x,a1.y,a1.z,a1.w};
        float br[4] = {b0.x,b0.y,b0.z,b0.w};
        #pragma unroll
        for (int i = 0; i < 8; i++)
            #pragma unroll
            for (int j = 0; j < 4; j++)
                acc[i][j] = fmaf(ar[i], br[j], acc[i][j]);
    }

    float p1x[4], p1y[4], p1z[4], n1v[4];
    #pragma unroll
    for (int j = 0; j < 4; j++) {
        int cj = cb + j;
        p1x[j] = P1[cj]; p1y[j] = P1[64+cj]; p1z[j] = P1[128+cj];
        n1v[j] = N1s[cj];
    }
    float eps = __expf(epsilon[0]) + 0.025f;
    float inv_eps = 1.0f/eps;
    float cs[4] = {0.f, 0.f, 0.f, 0.f};
    #pragma unroll
    for (int i = 0; i < 8; i++) {
        int ri = rb + ((i < 4) ? i : 60 + i);     // i>=4 -> rb+64+(i-4)
        float p0x = P0[ri], p0y = P0[128+ri], p0z = P0[256+ri];
        float n0v = N0s[ri];
        float kv[4];
        #pragma unroll
        for (int j = 0; j < 4; j++) {
            float pd  = fmaf(p0x, p1x[j], fmaf(p0y, p1y[j], p0z*p1z[j]));
            float sqd = n0v + n1v[j] - 2.0f*pd;
            float v   = (sqd < 100.0f) ? __expf((acc[i][j] - 1.0f)*inv_eps) : 0.0f;
            kv[j] = v; cs[j] += v;
        }
        size_t base = ((size_t)(bz*NNPTS) + row0 + ri)*NNPTS + col0;
        *(float4*)&g_K[base + cb] = make_float4(kv[0],kv[1],kv[2],kv[3]);
    }
    #pragma unroll
    for (int j = 0; j < 4; j++) atomicAdd(&colpart[cb+j], cs[j]);
    __syncthreads();
    if (tid < 64) atomicAdd(&g_colsum[bz*NNPTS + col0 + tid], colpart[tid]);
}

// -------- b vector, stored transposed for rowpass ------------------------
__global__ __launch_bounds__(256)
void bvec_kernel(const float* __restrict__ pc1,
                 const float* __restrict__ gamma, const float* __restrict__ epsilon)
{
    int i = blockIdx.x*blockDim.x + threadIdx.x;
    if (i >= NTOT) return;
    float eps = expf(epsilon[0]) + 0.025f;
    float gam = expf(gamma[0]);
    float power = gam/(gam+eps);
    float kta = g_colsum[i] * (1.0f/NNPTS);
    float b = powf((1.0f/NNPTS)/(kta + 1e-8f), power);
    int bz = i / NNPTS, c = i % NNPTS;
    g_w4t[bz*NNPTS + (c & 3)*1024 + (c >> 2)] =
        make_float4(b, b*pc1[i*3+0], b*pc1[i*3+1], b*pc1[i*3+2]);
}

// ---------------- row pass: Kb, K b pc1 -> ot_flow ------------------------
__global__ __launch_bounds__(256)
void rowpass_kernel(const float* __restrict__ pc0,
                    const float* __restrict__ gamma, const float* __restrict__ epsilon)
{
    __shared__ float rbuf[8][4][4];
    int tid = threadIdx.x;
    int r0 = blockIdx.x * 4;
    int bz = r0 / NNPTS;
    const float4* wt = g_w4t + bz*NNPTS;
    int wid = tid >> 5, lane = tid & 31;

    const float4* K0 = (const float4*)(g_K + (size_t)(r0+0)*NNPTS);
    const float4* K1 = (const float4*)(g_K + (size_t)(r0+1)*NNPTS);
    const float4* K2 = (const float4*)(g_K + (size_t)(r0+2)*NNPTS);
    const float4* K3 = (const float4*)(g_K + (size_t)(r0+3)*NNPTS);
    float acc[4][4];
    #pragma unroll
    for (int r = 0; r < 4; r++)
        acc[r][0]=acc[r][1]=acc[r][2]=acc[r][3]=0.f;
    #pragma unroll
    for (int i = 0; i < 4; i++) {
        int f = tid + i*256;
        float4 w0 = __ldg(&wt[f]),      float4_w1_dummy = {};
        (void)float4_w1_dummy;
        float4 w1 = __ldg(&wt[1024+f]);
        float4 w2 = __ldg(&wt[2048+f]), w3 = __ldg(&wt[3072+f]);
        float4 kr[4] = { K0[f], K1[f], K2[f], K3[f] };
        #pragma unroll
        for (int r = 0; r < 4; r++) {
            float4 k = kr[r];
            acc[r][0] = fmaf(k.x,w0.x, fmaf(k.y,w1.x, fmaf(k.z,w2.x, fmaf(k.w,w3.x, acc[r][0]))));
            acc[r][1] = fmaf(k.x,w0.y, fmaf(k.y,w1.y, fmaf(k.z,w2.y, fmaf(k.w,w3.y, acc[r][1]))));
            acc[r][2] = fmaf(k.x,w0.z, fmaf(k.y,w1.z, fmaf(k.z,w2.z, fmaf(k.w,w3.z, acc[r][2]))));
            acc[r][3] = fmaf(k.x,w0.w, fmaf(k.y,w1.w, fmaf(k.z,w2.w, fmaf(k.w,w3.w, acc[r][3]))));
        }
    }
    #pragma unroll
    for (int r = 0; r < 4; r++) {
        #pragma unroll
        for (int o = 16; o > 0; o >>= 1) {
            acc[r][0] += __shfl_xor_sync(0xffffffffu, acc[r][0], o);
            acc[r][1] += __shfl_xor_sync(0xffffffffu, acc[r][1], o);
            acc[r][2] += __shfl_xor_sync(0xffffffffu, acc[r][2], o);
            acc[r][3] += __shfl_xor_sync(0xffffffffu, acc[r][3], o);
        }
        if (lane == 0) {
            rbuf[wid][r][0]=acc[r][0]; rbuf[wid][r][1]=acc[r][1];
            rbuf[wid][r][2]=acc[r][2]; rbuf[wid][r][3]=acc[r][3];
        }
    }
    __syncthreads();
    if (tid < 4) {
        int r = tid;
        float Kb=0.f,Sx=0.f,Sy=0.f,Sz=0.f;
        #pragma unroll
        for (int w = 0; w < 8; w++) {
            Kb += rbuf[w][r][0]; Sx += rbuf[w][r][1];
            Sy += rbuf[w][r][2]; Sz += rbuf[w][r][3];
        }
        float eps = expf(epsilon[0]) + 0.025f;
        float gam = expf(gamma[0]);
        float power = gam/(gam+eps);
        float a  = powf((1.0f/NNPTS)/(Kb + 1e-8f), power);
        float rs = a*Kb;
        float inv = 1.0f/(rs + 1e-8f);
        int row = r0 + r;
        g_otflow[row*3+0] = a*Sx*inv - pc0[row*3+0];
        g_otflow[row*3+1] = a*Sy*inv - pc0[row*3+1];
        g_otflow[row*3+2] = a*Sz*inv - pc0[row*3+2];
    }
}

// ---------------- conv1: edge conv (6->32->32->32) + y2 epilogue ---------
__global__ __launch_bounds__(256)
void conv1_kernel(const float* __restrict__ pc0,
                  const float* __restrict__ W1, const float* __restrict__ B1,
                  const float* __restrict__ W2, const float* __restrict__ B2,
                  const float* __restrict__ W3, const float* __restrict__ B3,
                  const float* __restrict__ W2a)   // w2_1 (35x64), rows 0..31
{
    __shared__ __align__(16) float in_s[8][KNN][8];
    __shared__ float h[8][32];
    __shared__ float h2[8][32];
    __shared__ int   nb_s[8][KNN];

    int tid = threadIdx.x;
    int g = tid >> 5, c = tid & 31;
    int node = blockIdx.x*8 + g;
    int b = node / NNPTS;

    nb_s[g][c] = g_idx[node*KNN + c];
    __syncthreads();

    for (int e = c; e < KNN*6; e += 32) {
        int j = e / 6, k = e % 6;
        int nb = nb_s[g][j];
        float v;
        if (k < 3) v = g_otflow[(b*NNPTS + nb)*3 + k];
        else       v = pc0[(b*NNPTS + nb)*3 + (k-3)] - pc0[node*3 + (k-3)];
        in_s[g][j][k] = v;
    }
    __syncthreads();

    float acc[KNN];
    float bias1 = B1[c];
    #pragma unroll
    for (int j = 0; j < KNN; j++) acc[j] = bias1;
    #pragma unroll
    for (int k = 0; k < 6; k++) {
        float w = W1[k*32 + c];
        #pragma unroll
        for (int j = 0; j < KNN; j++) acc[j] = fmaf(in_s[g][j][k], w, acc[j]);
    }
    float mx = -3.4e38f;
    #pragma unroll
    for (int j = 0; j < KNN; j++) mx = fmaxf(mx, lrelu(acc[j]));
    h[g][c] = mx;
    __syncthreads();

    float a2 = B2[c];
    for (int k = 0; k < 32; k++) a2 = fmaf(h[g][k], W2[k*32 + c], a2);
    h2[g][c] = lrelu(a2);
    __syncthreads();

    float a3 = B3[c];
    for (int k = 0; k < 32; k++) a3 = fmaf(h2[g][k], W3[k*32 + c], a3);
    h[g][c] = lrelu(a3);
    __syncthreads();

    // y2 epilogue: y2 = x1 @ W2a (32 -> 64), 2 outputs per thread
    #pragma unroll
    for (int t = 0; t < 2; t++) {
        int cc = c + t*32;
        float y = 0.f;
        for (int k = 0; k < 32; k++) y = fmaf(h[g][k], W2a[k*64 + cc], y);
        g_y2[(size_t)node*64 + cc] = y;
    }
}

// ---------------- conv2: gather y2 + edge (3ch) -> 64, dense x2, y3 epi --
__global__ __launch_bounds__(256)
void conv2_kernel(const float* __restrict__ pc0,
                  const float* __restrict__ W1, const float* __restrict__ B1, // w2_1, b2_1
                  const float* __restrict__ W2, const float* __restrict__ B2,
                  const float* __restrict__ W3, const float* __restrict__ B3,
                  const float* __restrict__ W3a)   // w3_1 (67x128), rows 0..63
{
    __shared__ int    nb_s[4][KNN];
    __shared__ float4 es[4][KNN];
    __shared__ float  h[4][64];
    __shared__ float  h2[4][64];

    int tid = threadIdx.x;
    int g = tid >> 6, c = tid & 63;
    int node = blockIdx.x*4 + g;
    int b = node / NNPTS;

    if (c < KNN) {
        int nb = g_idx[node*KNN + c];
        nb_s[g][c] = nb;
        es[g][c] = make_float4(pc0[(b*NNPTS+nb)*3+0] - pc0[node*3+0],
                               pc0[(b*NNPTS+nb)*3+1] - pc0[node*3+1],
                               pc0[(b*NNPTS+nb)*3+2] - pc0[node*3+2], 0.f);
    }
    __syncthreads();

    const float* yb = g_y2 + (size_t)b*NNPTS*64;
    float yv[KNN];
    #pragma unroll
    for (int j = 0; j < KNN; j++) yv[j] = yb[nb_s[g][j]*64 + c];

    float wb0 = W1[32*64 + c], wb1 = W1[33*64 + c], wb2 = W1[34*64 + c];
    float bias = B1[c];
    float mx = -3.4e38f;
    #pragma unroll
    for (int j = 0; j < KNN; j++) {
        float4 e = es[g][j];
        float a = yv[j] + fmaf(e.x, wb0, fmaf(e.y, wb1, fmaf(e.z, wb2, bias)));
        mx = fmaxf(mx, lrelu(a));
    }
    h[g][c] = mx;
    __syncthreads();

    float a2 = B2[c];
    for (int k = 0; k < 64; k++) a2 = fmaf(h[g][k], W2[k*64 + c], a2);
    h2[g][c] = lrelu(a2);
    __syncthreads();

    float a3 = B3[c];
    for (int k = 0; k < 64; k++) a3 = fmaf(h2[g][k], W3[k*64 + c], a3);
    h[g][c] = lrelu(a3);
    __syncthreads();

    // y3 epilogue: y3 = x2 @ W3a (64 -> 128), 2 outputs per thread
    #pragma unroll
    for (int t = 0; t < 2; t++) {
        int cc = c + t*64;
        float y = 0.f;
        for (int k = 0; k < 64; k++) y = fmaf(h[g][k], W3a[k*128 + cc], y);
        g_y3[(size_t)node*128 + cc] = y;
    }
}

// ---------------- conv3: gather y3 + edge -> 128, dense, fc, residual ----
__global__ __launch_bounds__(256)
void conv3_kernel(const float* __restrict__ pc0,
                  const float* __restrict__ W1, const float* __restrict__ B1, // w3_1, b3_1
                  const float* __restrict__ W2, const float* __restrict__ B2,
                  const float* __restrict__ W3, const float* __restrict__ B3,
                  const float* __restrict__ Wfc, const float* __restrict__ Bfc,
                  float* __restrict__ dout)
{
    __shared__ int    nb_s[2][KNN];
    __shared__ float4 es[2][KNN];
    __shared__ float  h[2][128];
    __shared__ float  h2[2][128];

    int tid = threadIdx.x;
    int g = tid >> 7, c = tid & 127;
    int node = blockIdx.x*2 + g;
    int b = node / NNPTS;

    if (c < KNN) {
        int nb = g_idx[node*KNN + c];
        nb_s[g][c] = nb;
        es[g][c] = make_float4(pc0[(b*NNPTS+nb)*3+0] - pc0[node*3+0],
                               pc0[(b*NNPTS+nb)*3+1] - pc0[node*3+1],
                               pc0[(b*NNPTS+nb)*3+2] - pc0[node*3+2], 0.f);
    }
    __syncthreads();

    const float* yb = g_y3 + (size_t)b*NNPTS*128;
    float yv[KNN];
    #pragma unroll
    for (int j = 0; j < KNN; j++) yv[j] = yb[nb_s[g][j]*128 + c];

    float wb0 = W1[64*128 + c], wb1 = W1[65*128 + c], wb2 = W1[66*128 + c];
    float bias = B1[c];
    float mx = -3.4e38f;
    #pragma unroll
    for (int j = 0; j < KNN; j++) {
        float4 e = es[g][j];
        float a = yv[j] + fmaf(e.x, wb0, fmaf(e.y, wb1, fmaf(e.z, wb2, bias)));
        mx = fmaxf(mx, lrelu(a));
    }
    h[g][c] = mx;
    __syncthreads();

    float a2 = B2[c];
    for (int k = 0; k < 128; k++) a2 = fmaf(h[g][k], W2[k*128 + c], a2);
    h2[g][c] = lrelu(a2);
    __syncthreads();

    float a3 = B3[c];
    for (int k = 0; k < 128; k++) a3 = fmaf(h2[g][k], W3[k*128 + c], a3);
    h[g][c] = lrelu(a3);
    __syncthreads();

    if (c < 3) {
        float o = Bfc[c];
        for (int k = 0; k < 128; k++) o = fmaf(h[g][k], Wfc[k*3 + c], o);
        dout[node*3 + c] = g_otflow[node*3 + c] + o;
    }
}

// ---------------- launch --------------------------------------------------
extern "C" void kernel_launch(void* const* d_in, const int* in_sizes, int n_in,
                              void* d_out, int out_size)
{
    const float* pc0   = (const float*)d_in[0];
    const float* pc1   = (const float*)d_in[1];
    const float* f0    = (const float*)d_in[2];
    const float* f1    = (const float*)d_in[3];
    const float* gamma = (const float*)d_in[4];
    const float* eps   = (const float*)d_in[5];
    const float* w1_1=(const float*)d_in[6],  *b1_1=(const float*)d_in[7];
    const float* w1_2=(const float*)d_in[8],  *b1_2=(const float*)d_in[9];
    const float* w1_3=(const float*)d_in[10], *b1_3=(const float*)d_in[11];
    const float* w2_1=(const float*)d_in[12], *b2_1=(const float*)d_in[13];
    const float* w2_2=(const float*)d_in[14], *b2_2=(const float*)d_in[15];
    const float* w2_3=(const float*)d_in[16], *b2_3=(const float*)d_in[17];
    const float* w3_1=(const float*)d_in[18], *b3_1=(const float*)d_in[19];
    const float* w3_2=(const float*)d_in[20], *b3_2=(const float*)d_in[21];
    const float* w3_3=(const float*)d_in[22], *b3_3=(const float*)d_in[23];
    const float* wfc =(const float*)d_in[24], *bfc =(const float*)d_in[25];
    float* out = (float*)d_out;

    cudaFuncSetAttribute(kmat_kernel, cudaFuncAttributeMaxDynamicSharedMemorySize, 55296);

    prep_norm_kernel<<<(2*NTOT + 255)/256, 256>>>(pc0, pc1);      // 1
    knn_kernel<<<NTOT, 256>>>();                                   // 2
    prep_feat_kernel<<<2048, 256>>>(f0, f1);                       // 3
    kmat_kernel<<<dim3(NNPTS/64, NNPTS/128, BB), 256, 54528>>>(pc0, pc1, eps); // 4 = ncu slot
    bvec_kernel<<<(NTOT + 255)/256, 256>>>(pc1, gamma, eps);
    rowpass_kernel<<<NTOT/4, 256>>>(pc0, gamma, eps);
    conv1_kernel<<<NTOT/8, 256>>>(pc0, w1_1,b1_1, w1_2,b1_2, w1_3,b1_3, w2_1);
    conv2_kernel<<<NTOT/4, 256>>>(pc0, w2_1,b2_1, w2_2,b2_2, w2_3,b2_3, w3_1);
    conv3_kernel<<<NTOT/2, 256>>>(pc0, w3_1,b3_1, w3_2,b3_2, w3_3,b3_3, wfc,bfc, out);
}

// round 15
// speedup vs baseline: 1.1049x; 1.1049x over previous
#include <cuda_runtime.h>
#include <cuda_bf16.h>
#include <math.h>
#include <stdint.h>

#define BB 2
#define NNPTS 4096
#define CF 64
#define KNN 32
#define NTOT (BB*NNPTS)

// ---------------- scratch (static __device__, no allocs) ----------------
__device__ float  g_K[(size_t)BB*NNPTS*NNPTS];     // 128 MB transport kernel
__device__ unsigned short g_a16[(size_t)NTOT*192]; // split-bf16 A rows [hi|hi|lo]
__device__ unsigned short g_b16[(size_t)NTOT*192]; // split-bf16 B rows [hi|lo|hi]
__device__ float  g_n0[NTOT];
__device__ float  g_n1[NTOT];
__device__ float4 g_pts0[NTOT];
__device__ float  g_colsum[NTOT];
__device__ float4 g_w4t[NTOT];
__device__ float  g_otflow[NTOT*3];
__device__ int    g_idx[NTOT*KNN];
__device__ float  g_y2[NTOT*64];
__device__ float  g_y3[NTOT*128];

__device__ __forceinline__ float lrelu(float x){ return (x > 0.f) ? x : 0.1f*x; }

// ---------------- prep 1: point norms + packed pts + colsum zero ---------
__global__ __launch_bounds__(256)
void prep_norm_kernel(const float* __restrict__ pc0, const float* __restrict__ pc1)
{
    int i = blockIdx.x*blockDim.x + threadIdx.x;
    if (i >= 2*NTOT) return;
    int which = i / NTOT, row = i % NTOT;
    const float* pc = which ? pc1 : pc0;
    float x = pc[row*3+0], y = pc[row*3+1], z = pc[row*3+2];
    float n2 = x*x + y*y + z*z;
    if (which) g_n1[row] = n2;
    else {
        g_n0[row] = n2; g_colsum[row] = 0.f;
        g_pts0[row] = make_float4(x, y, z, n2);
    }
}

// ---- prep 2: normalize + split-bf16 row-major images --------------------
__global__ __launch_bounds__(256)
void prep_feat_kernel(const float* __restrict__ f0, const float* __restrict__ f1)
{
    int w    = (blockIdx.x*blockDim.x + threadIdx.x) >> 5;
    int lane = threadIdx.x & 31;
    if (w >= 2*NTOT) return;
    int which = w / NTOT;
    int row   = w % NTOT;
    const float* f = which ? f1 : f0;
    float v0 = f[row*CF + lane];
    float v1 = f[row*CF + 32 + lane];
    float ss = v0*v0 + v1*v1;
    #pragma unroll
    for (int o = 16; o > 0; o >>= 1) ss += __shfl_xor_sync(0xffffffffu, ss, o);
    float inv = rsqrtf(ss + 1e-8f);
    v0 *= inv; v1 *= inv;

    unsigned short* base = (which ? g_b16 : g_a16) + (size_t)row*192;
    #pragma unroll
    for (int t = 0; t < 2; t++) {
        int c = lane + t*32;
        float v = t ? v1 : v0;
        __nv_bfloat16 h = __float2bfloat16(v);
        unsigned short hb = __bfloat16_as_ushort(h);
        unsigned short lb = __bfloat16_as_ushort(__float2bfloat16(v - __bfloat162float(h)));
        if (!which) { base[c] = hb; base[64+c] = hb; base[128+c] = lb; }   // A: hi|hi|lo
        else        { base[c] = hb; base[64+c] = lb; base[128+c] = hb; }   // B: hi|lo|hi
    }
}

// ---------------- KNN: radix-select 32 smallest sqdists per row ----------
__global__ __launch_bounds__(256)
void knn_kernel()
{
    int n = blockIdx.x; int b = n / NNPTS;
    const float4* pts = g_pts0 + b*NNPTS;
    int tid = threadIdx.x;
    int lane = tid & 31;
    float4 q = g_pts0[n];
    unsigned key[16];
    #pragma unroll
    for (int i = 0; i < 16; i++) {
        float4 p = pts[tid + i*256];
        float dot = fmaf(p.x, q.x, fmaf(p.y, q.y, p.z*q.z));
        float d = q.w + p.w - 2.0f*dot;
        unsigned u = __float_as_uint(d);
        u = (u & 0x80000000u) ? ~u : (u | 0x80000000u);
        key[i] = u;
    }
    __shared__ int hist[256];
    __shared__ unsigned s_prefix;
    __shared__ int s_krem, s_cl, s_ct;
    __shared__ int s_out[KNN];
    __shared__ int s_tie[64];
    if (tid == 0) { s_prefix = 0u; s_krem = KNN; s_cl = 0; s_ct = 0; }
    for (int r = 0; r < 4; r++) {
        int shift = 24 - 8*r;
        hist[tid] = 0;
        __syncthreads();
        unsigned pref = s_prefix;
        unsigned msk  = (r == 0) ? 0u : (0xFFFFFFFFu << (32 - 8*r));
        #pragma unroll
        for (int i = 0; i < 16; i++)
            if ((key[i] & msk) == (pref & msk))
                atomicAdd(&hist[(key[i] >> shift) & 255], 1);
        __syncthreads();
        if (tid < 32) {
            int krem = s_krem;
            int loc[8]; int tot = 0;
            #pragma unroll
            for (int j = 0; j < 8; j++) { loc[j] = hist[tid*8 + j]; tot += loc[j]; }
            int incl = tot;
            #pragma unroll
            for (int o = 1; o < 32; o <<= 1) {
                int x = __shfl_up_sync(0xffffffffu, incl, o);
                if (lane >= o) incl += x;
            }
            int excl = incl - tot;
            if (excl < krem && krem <= incl) {
                int rem = krem - excl;
                int d = 0;
                #pragma unroll
                for (int j = 0; j < 7; j++) if (rem > loc[d]) { rem -= loc[d]; d++; }
                s_prefix = pref | ((unsigned)(tid*8 + d) << shift);
                s_krem = rem;
            }
        }
        __syncthreads();
    }
    unsigned pivot = s_prefix;
    #pragma unroll
    for (int i = 0; i < 16; i++) {
        unsigned u = key[i];
        if (u < pivot)       { int p = atomicAdd(&s_cl, 1); s_out[p] = tid + i*256; }
        else if (u == pivot) { int t = atomicAdd(&s_ct, 1); if (t < 64) s_tie[t] = tid + i*256; }
    }
    __syncthreads();
    if (tid == 0) {
        int cl = s_cl;
        int nt = (s_ct < 64) ? s_ct : 64;
        int need = KNN - cl;
        for (int s = 0; s < need; s++) {
            int best = 0x7FFFFFFF, bi = 0;
            for (int t = 0; t < nt; t++) if (s_tie[t] < best) { best = s_tie[t]; bi = t; }
            s_tie[bi] = 0x7FFFFFFF;
            s_out[cl + s] = best;
        }
    }
    __syncthreads();
    if (tid < KNN) g_idx[n*KNN + tid] = s_out[tid];
}

// ------- kmat: bf16 split GEMM via mma.sync m16n8k16 + exp epilogue ------
// Tile 128x64, 8 warps (4 row x 2 col), each warp 32x32 (2x4 mma tiles).
// smem: A 128x200 bf16 (51200 B), B 64x200 bf16 (25600), P/N arrays, D reuse A.
__device__ __forceinline__ void mma16816(float* d, const uint32_t* a, const uint32_t* b)
{
    asm volatile(
        "mma.sync.aligned.m16n8k16.row.col.f32.bf16.bf16.f32 "
        "{%0,%1,%2,%3}, {%4,%5,%6,%7}, {%8,%9}, {%0,%1,%2,%3};"
        : "+f"(d[0]), "+f"(d[1]), "+f"(d[2]), "+f"(d[3])
        : "r"(a[0]), "r"(a[1]), "r"(a[2]), "r"(a[3]), "r"(b[0]), "r"(b[1]));
}

__global__ __launch_bounds__(256, 2)
void kmat_kernel(const float* __restrict__ pc0, const float* __restrict__ pc1,
                 const float* __restrict__ epsilon)
{
    extern __shared__ char smem[];
    unsigned short* As = (unsigned short*)smem;            // stride 200
    unsigned short* Bs = (unsigned short*)(smem + 51200);  // stride 200
    float* P0  = (float*)(smem + 76800);   // 3*128
    float* P1  = (float*)(smem + 78336);   // 3*64
    float* N0s = (float*)(smem + 79104);   // 128
    float* N1s = (float*)(smem + 79616);   // 64

    int tid = threadIdx.x, wid = tid >> 5, lane = tid & 31;
    int g = lane >> 2, t = lane & 3;
    int bz = blockIdx.z;
    int row0 = blockIdx.y*128, col0 = blockIdx.x*64;

    {   // A copy: 128 rows x 384 B (row-major gmem -> stride-400 smem)
        const char* src = (const char*)(g_a16 + ((size_t)(bz*NNPTS) + row0)*192);
        #pragma unroll
        for (int i = 0; i < 12; i++) {
            int idx = tid + i*256;               // 0..3071 float4 slots
            int row = idx / 24, j = idx - row*24;
            float4 v = *(const float4*)(src + row*384 + j*16);
            *(float4*)(smem + row*400 + j*16) = v;
        }
        const char* srcb = (const char*)(g_b16 + ((size_t)(bz*NNPTS) + col0)*192);
        #pragma unroll
        for (int i = 0; i < 6; i++) {
            int idx = tid + i*256;               // 0..1535
            int row = idx / 24, j = idx - row*24;
            float4 v = *(const float4*)(srcb + row*384 + j*16);
            *(float4*)(smem + 51200 + row*400 + j*16) = v;
        }
    }
    if (tid < 128) {
        int r = tid;
        #pragma unroll
        for (int d = 0; d < 3; d++) P0[d*128 + r] = pc0[(bz*NNPTS+row0+r)*3 + d];
        N0s[r] = g_n0[bz*NNPTS + row0 + r];
    } else if (tid < 192) {
        int r = tid - 128;
        #pragma unroll
        for (int d = 0; d < 3; d++) P1[d*64 + r] = pc1[(bz*NNPTS+col0+r)*3 + d];
        N1s[r] = g_n1[bz*NNPTS + col0 + r];
    }
    __syncthreads();

    int wr = wid >> 1, wc = wid & 1;
    float acc[2][4][4];
    #pragma unroll
    for (int mi = 0; mi < 2; mi++)
        #pragma unroll
        for (int ni = 0; ni < 4; ni++)
            acc[mi][ni][0]=acc[mi][ni][1]=acc[mi][ni][2]=acc[mi][ni][3]=0.f;

    #pragma unroll 2
    for (int k0 = 0; k0 < 192; k0 += 16) {
        uint32_t a[2][4];
        #pragma unroll
        for (int mi = 0; mi < 2; mi++) {
            const unsigned short* ap = As + (wr*32 + mi*16 + g)*200 + k0 + t*2;
            a[mi][0] = *(const uint32_t*)(ap);
            a[mi][1] = *(const uint32_t*)(ap + 8*200);
            a[mi][2] = *(const uint32_t*)(ap + 8);
            a[mi][3] = *(const uint32_t*)(ap + 8*200 + 8);
        }
        uint32_t b[4][2];
        #pragma unroll
        for (int ni = 0; ni < 4; ni++) {
            const unsigned short* bp = Bs + (wc*32 + ni*8 + g)*200 + k0 + t*2;
            b[ni][0] = *(const uint32_t*)(bp);
            b[ni][1] = *(const uint32_t*)(bp + 8);
        }
        #pragma unroll
        for (int mi = 0; mi < 2; mi++)
            #pragma unroll
            for (int ni = 0; ni < 4; ni++)
                mma16816(acc[mi][ni], a[mi], b[ni]);
    }
    __syncthreads();                         // done reading A/B; reuse A as D

    float* D = (float*)smem;                 // [128][65]
    {
        float eps = __expf(epsilon[0]) + 0.025f;
        float inv_eps = 1.0f/eps;
        #pragma unroll
        for (int mi = 0; mi < 2; mi++) {
            int rA = wr*32 + mi*16 + g;
            #pragma unroll
            for (int half = 0; half < 2; half++) {
                int r = rA + half*8;
                float p0x = P0[r], p0y = P0[128+r], p0z = P0[256+r];
                float n0v = N0s[r];
                #pragma unroll
                for (int ni = 0; ni < 4; ni++) {
                    #pragma unroll
                    for (int cc = 0; cc < 2; cc++) {
                        int c = wc*32 + ni*8 + t*2 + cc;
                        float dot = acc[mi][ni][half*2 + cc];
                        float pd  = fmaf(p0x, P1[c], fmaf(p0y, P1[64+c], p0z*P1[128+c]));
                        float sqd = n0v + N1s[c] - 2.0f*pd;
                        D[r*65 + c] = (sqd < 100.0f) ? __expf((dot - 1.0f)*inv_eps) : 0.0f;
                    }
                }
            }
        }
    }
    __syncthreads();
    {   // coalesced store of D tile (128x64)
        #pragma unroll
        for (int it = 0; it < 8; it++) {
            int idx = tid + it*256;
            int row = idx >> 4, c4 = (idx & 15)*4;
            const float* s = D + row*65 + c4;
            float4 v = make_float4(s[0], s[1], s[2], s[3]);
            *(float4*)&g_K[((size_t)(bz*NNPTS) + row0 + row)*NNPTS + col0 + c4] = v;
        }
    }
    if (tid < 64) {                          // column sums of this tile
        float s = 0.f;
        #pragma unroll 8
        for (int r = 0; r < 128; r++) s += D[r*65 + tid];
        atomicAdd(&g_colsum[bz*NNPTS + col0 + tid], s);
    }
}

// -------- b vector, stored transposed for rowpass ------------------------
__global__ __launch_bounds__(256)
void bvec_kernel(const float* __restrict__ pc1,
                 const float* __restrict__ gamma, const float* __restrict__ epsilon)
{
    int i = blockIdx.x*blockDim.x + threadIdx.x;
    if (i >= NTOT) return;
    float eps = expf(epsilon[0]) + 0.025f;
    float gam = expf(gamma[0]);
    float power = gam/(gam+eps);
    float kta = g_colsum[i] * (1.0f/NNPTS);
    float b = powf((1.0f/NNPTS)/(kta + 1e-8f), power);
    int bz = i / NNPTS, c = i % NNPTS;
    g_w4t[bz*NNPTS + (c & 3)*1024 + (c >> 2)] =
        make_float4(b, b*pc1[i*3+0], b*pc1[i*3+1], b*pc1[i*3+2]);
}

// ---------------- row pass: Kb, K b pc1 -> ot_flow ------------------------
__global__ __launch_bounds__(256)
void rowpass_kernel(const float* __restrict__ pc0,
                    const float* __restrict__ gamma, const float* __restrict__ epsilon)
{
    __shared__ float rbuf[8][4][4];
    int tid = threadIdx.x;
    int r0 = blockIdx.x * 4;
    int bz = r0 / NNPTS;
    const float4* wt = g_w4t + bz*NNPTS;
    int wid = tid >> 5, lane = tid & 31;

    const float4* K0 = (const float4*)(g_K + (size_t)(r0+0)*NNPTS);
    const float4* K1 = (const float4*)(g_K + (size_t)(r0+1)*NNPTS);
    const float4* K2 = (const float4*)(g_K + (size_t)(r0+2)*NNPTS);
    const float4* K3 = (const float4*)(g_K + (size_t)(r0+3)*NNPTS);
    float acc[4][4];
    #pragma unroll
    for (int r = 0; r < 4; r++)
        acc[r][0]=acc[r][1]=acc[r][2]=acc[r][3]=0.f;
    #pragma unroll
    for (int i = 0; i < 4; i++) {
        int f = tid + i*256;
        float4 w0 = __ldg(&wt[f]),      w1 = __ldg(&wt[1024+f]);
        float4 w2 = __ldg(&wt[2048+f]), w3 = __ldg(&wt[3072+f]);
        float4 kr[4] = { K0[f], K1[f], K2[f], K3[f] };
        #pragma unroll
        for (int r = 0; r < 4; r++) {
            float4 k = kr[r];
            acc[r][0] = fmaf(k.x,w0.x, fmaf(k.y,w1.x, fmaf(k.z,w2.x, fmaf(k.w,w3.x, acc[r][0]))));
            acc[r][1] = fmaf(k.x,w0.y, fmaf(k.y,w1.y, fmaf(k.z,w2.y, fmaf(k.w,w3.y, acc[r][1]))));
            acc[r][2] = fmaf(k.x,w0.z, fmaf(k.y,w1.z, fmaf(k.z,w2.z, fmaf(k.w,w3.z, acc[r][2]))));
            acc[r][3] = fmaf(k.x,w0.w, fmaf(k.y,w1.w, fmaf(k.z,w2.w, fmaf(k.w,w3.w, acc[r][3]))));
        }
    }
    #pragma unroll
    for (int r = 0; r < 4; r++) {
        #pragma unroll
        for (int o = 16; o > 0; o >>= 1) {
            acc[r][0] += __shfl_xor_sync(0xffffffffu, acc[r][0], o);
            acc[r][1] += __shfl_xor_sync(0xffffffffu, acc[r][1], o);
            acc[r][2] += __shfl_xor_sync(0xffffffffu, acc[r][2], o);
            acc[r][3] += __shfl_xor_sync(0xffffffffu, acc[r][3], o);
        }
        if (lane == 0) {
            rbuf[wid][r][0]=acc[r][0]; rbuf[wid][r][1]=acc[r][1];
            rbuf[wid][r][2]=acc[r][2]; rbuf[wid][r][3]=acc[r][3];
        }
    }
    __syncthreads();
    if (tid < 4) {
        int r = tid;
        float Kb=0.f,Sx=0.f,Sy=0.f,Sz=0.f;
        #pragma unroll
        for (int w = 0; w < 8; w++) {
            Kb += rbuf[w][r][0]; Sx += rbuf[w][r][1];
            Sy += rbuf[w][r][2]; Sz += rbuf[w][r][3];
        }
        float eps = expf(epsilon[0]) + 0.025f;
        float gam = expf(gamma[0]);
        float power = gam/(gam+eps);
        float a  = powf((1.0f/NNPTS)/(Kb + 1e-8f), power);
        float rs = a*Kb;
        float inv = 1.0f/(rs + 1e-8f);
        int row = r0 + r;
        g_otflow[row*3+0] = a*Sx*inv - pc0[row*3+0];
        g_otflow[row*3+1] = a*Sy*inv - pc0[row*3+1];
        g_otflow[row*3+2] = a*Sz*inv - pc0[row*3+2];
    }
}

// ---------------- conv1: edge conv (6->32->32->32) + y2 epilogue ---------
__global__ __launch_bounds__(256)
void conv1_kernel(const float* __restrict__ pc0,
                  const float* __restrict__ W1, const float* __restrict__ B1,
                  const float* __restrict__ W2, const float* __restrict__ B2,
                  const float* __restrict__ W3, const float* __restrict__ B3,
                  const float* __restrict__ W2a)
{
    __shared__ __align__(16) float in_s[8][KNN][8];
    __shared__ float h[8][32];
    __shared__ float h2[8][32];
    __shared__ int   nb_s[8][KNN];

    int tid = threadIdx.x;
    int g = tid >> 5, c = tid & 31;
    int node = blockIdx.x*8 + g;
    int b = node / NNPTS;

    nb_s[g][c] = g_idx[node*KNN + c];
    __syncthreads();

    for (int e = c; e < KNN*6; e += 32) {
        int j = e / 6, k = e % 6;
        int nb = nb_s[g][j];
        float v;
        if (k < 3) v = g_otflow[(b*NNPTS + nb)*3 + k];
        else       v = pc0[(b*NNPTS + nb)*3 + (k-3)] - pc0[node*3 + (k-3)];
        in_s[g][j][k] = v;
    }
    __syncthreads();

    float acc[KNN];
    float bias1 = B1[c];
    #pragma unroll
    for (int j = 0; j < KNN; j++) acc[j] = bias1;
    #pragma unroll
    for (int k = 0; k < 6; k++) {
        float w = W1[k*32 + c];
        #pragma unroll
        for (int j = 0; j < KNN; j++) acc[j] = fmaf(in_s[g][j][k], w, acc[j]);
    }
    float mx = -3.4e38f;
    #pragma unroll
    for (int j = 0; j < KNN; j++) mx = fmaxf(mx, lrelu(acc[j]));
    h[g][c] = mx;
    __syncthreads();

    float a2 = B2[c];
    for (int k = 0; k < 32; k++) a2 = fmaf(h[g][k], W2[k*32 + c], a2);
    h2[g][c] = lrelu(a2);
    __syncthreads();

    float a3 = B3[c];
    for (int k = 0; k < 32; k++) a3 = fmaf(h2[g][k], W3[k*32 + c], a3);
    h[g][c] = lrelu(a3);
    __syncthreads();

    #pragma unroll
    for (int t = 0; t < 2; t++) {
        int cc = c + t*32;
        float y = 0.f;
        for (int k = 0; k < 32; k++) y = fmaf(h[g][k], W2a[k*64 + cc], y);
        g_y2[(size_t)node*64 + cc] = y;
    }
}

// ---------------- conv2: gather y2 + edge -> 64, dense x2, y3 epi --------
__global__ __launch_bounds__(256)
void conv2_kernel(const float* __restrict__ pc0,
                  const float* __restrict__ W1, const float* __restrict__ B1,
                  const float* __restrict__ W2, const float* __restrict__ B2,
                  const float* __restrict__ W3, const float* __restrict__ B3,
                  const float* __restrict__ W3a)
{
    __shared__ int    nb_s[4][KNN];
    __shared__ float4 es[4][KNN];
    __shared__ float  h[4][64];
    __shared__ float  h2[4][64];

    int tid = threadIdx.x;
    int g = tid >> 6, c = tid & 63;
    int node = blockIdx.x*4 + g;
    int b = node / NNPTS;

    if (c < KNN) {
        int nb = g_idx[node*KNN + c];
        nb_s[g][c] = nb;
        es[g][c] = make_float4(pc0[(b*NNPTS+nb)*3+0] - pc0[node*3+0],
                               pc0[(b*NNPTS+nb)*3+1] - pc0[node*3+1],
                               pc0[(b*NNPTS+nb)*3+2] - pc0[node*3+2], 0.f);
    }
    __syncthreads();

    const float* yb = g_y2 + (size_t)b*NNPTS*64;
    float yv[KNN];
    #pragma unroll
    for (int j = 0; j < KNN; j++) yv[j] = yb[nb_s[g][j]*64 + c];

    float wb0 = W1[32*64 + c], wb1 = W1[33*64 + c], wb2 = W1[34*64 + c];
    float bias = B1[c];
    float mx = -3.4e38f;
    #pragma unroll
    for (int j = 0; j < KNN; j++) {
        float4 e = es[g][j];
        float a = yv[j] + fmaf(e.x, wb0, fmaf(e.y, wb1, fmaf(e.z, wb2, bias)));
        mx = fmaxf(mx, lrelu(a));
    }
    h[g][c] = mx;
    __syncthreads();

    float a2 = B2[c];
    for (int k = 0; k < 64; k++) a2 = fmaf(h[g][k], W2[k*64 + c], a2);
    h2[g][c] = lrelu(a2);
    __syncthreads();

    float a3 = B3[c];
    for (int k = 0; k < 64; k++) a3 = fmaf(h2[g][k], W3[k*64 + c], a3);
    h[g][c] = lrelu(a3);
    __syncthreads();

    #pragma unroll
    for (int t = 0; t < 2; t++) {
        int cc = c + t*64;
        float y = 0.f;
        for (int k = 0; k < 64; k++) y = fmaf(h[g][k], W3a[k*128 + cc], y);
        g_y3[(size_t)node*128 + cc] = y;
    }
}

// ---------------- conv3: gather y3 + edge -> 128, dense, fc, residual ----
__global__ __launch_bounds__(256)
void conv3_kernel(const float* __restrict__ pc0,
                  const float* __restrict__ W1, const float* __restrict__ B1,
                  const float* __restrict__ W2, const float* __restrict__ B2,
                  const float* __restrict__ W3, const float* __restrict__ B3,
                  const float* __restrict__ Wfc, const float* __restrict__ Bfc,
                  float* __restrict__ dout)
{
    __shared__ int    nb_s[2][KNN];
    __shared__ float4 es[2][KNN];
    __shared__ float  h[2][128];
    __shared__ float  h2[2][128];

    int tid = threadIdx.x;
    int g = tid >> 7, c = tid & 127;
    int node = blockIdx.x*2 + g;
    int b = node / NNPTS;

    if (c < KNN) {
        int nb = g_idx[node*KNN + c];
        nb_s[g][c] = nb;
        es[g][c] = make_float4(pc0[(b*NNPTS+nb)*3+0] - pc0[node*3+0],
                               pc0[(b*NNPTS+nb)*3+1] - pc0[node*3+1],
                               pc0[(b*NNPTS+nb)*3+2] - pc0[node*3+2], 0.f);
    }
    __syncthreads();

    const float* yb = g_y3 + (size_t)b*NNPTS*128;
    float yv[KNN];
    #pragma unroll
    for (int j = 0; j < KNN; j++) yv[j] = yb[nb_s[g][j]*128 + c];

    float wb0 = W1[64*128 + c], wb1 = W1[65*128 + c], wb2 = W1[66*128 + c];
    float bias = B1[c];
    float mx = -3.4e38f;
    #pragma unroll
    for (int j = 0; j < KNN; j++) {
        float4 e = es[g][j];
        float a = yv[j] + fmaf(e.x, wb0, fmaf(e.y, wb1, fmaf(e.z, wb2, bias)));
        mx = fmaxf(mx, lrelu(a));
    }
    h[g][c] = mx;
    __syncthreads();

    float a2 = B2[c];
    for (int k = 0; k < 128; k++) a2 = fmaf(h[g][k], W2[k*128 + c], a2);
    h2[g][c] = lrelu(a2);
    __syncthreads();

    float a3 = B3[c];
    for (int k = 0; k < 128; k++) a3 = fmaf(h2[g][k], W3[k*128 + c], a3);
    h[g][c] = lrelu(a3);
    __syncthreads();

    if (c < 3) {
        float o = Bfc[c];
        for (int k = 0; k < 128; k++) o = fmaf(h[g][k], Wfc[k*3 + c], o);
        dout[node*3 + c] = g_otflow[node*3 + c] + o;
    }
}

// ---------------- launch --------------------------------------------------
extern "C" void kernel_launch(void* const* d_in, const int* in_sizes, int n_in,
                              void* d_out, int out_size)
{
    const float* pc0   = (const float*)d_in[0];
    const float* pc1   = (const float*)d_in[1];
    const float* f0    = (const float*)d_in[2];
    const float* f1    = (const float*)d_in[3];
    const float* gamma = (const float*)d_in[4];
    const float* eps   = (const float*)d_in[5];
    const float* w1_1=(const float*)d_in[6],  *b1_1=(const float*)d_in[7];
    const float* w1_2=(const float*)d_in[8],  *b1_2=(const float*)d_in[9];
    const float* w1_3=(const float*)d_in[10], *b1_3=(const float*)d_in[11];
    const float* w2_1=(const float*)d_in[12], *b2_1=(const float*)d_in[13];
    const float* w2_2=(const float*)d_in[14], *b2_2=(const float*)d_in[15];
    const float* w2_3=(const float*)d_in[16], *b2_3=(const float*)d_in[17];
    const float* w3_1=(const float*)d_in[18], *b3_1=(const float*)d_in[19];
    const float* w3_2=(const float*)d_in[20], *b3_2=(const float*)d_in[21];
    const float* w3_3=(const float*)d_in[22], *b3_3=(const float*)d_in[23];
    const float* wfc =(const float*)d_in[24], *bfc =(const float*)d_in[25];
    float* out = (float*)d_out;

    cudaFuncSetAttribute(kmat_kernel, cudaFuncAttributeMaxDynamicSharedMemorySize, 80896);

    prep_norm_kernel<<<(2*NTOT + 255)/256, 256>>>(pc0, pc1);      // 1
    knn_kernel<<<NTOT, 256>>>();                                   // 2
    prep_feat_kernel<<<2048, 256>>>(f0, f1);                       // 3
    kmat_kernel<<<dim3(NNPTS/64, NNPTS/128, BB), 256, 79872>>>(pc0, pc1, eps); // 4 = ncu slot
    bvec_kernel<<<(NTOT + 255)/256, 256>>>(pc1, gamma, eps);
    rowpass_kernel<<<NTOT/4, 256>>>(pc0, gamma, eps);
    conv1_kernel<<<NTOT/8, 256>>>(pc0, w1_1,b1_1, w1_2,b1_2, w1_3,b1_3, w2_1);
    conv2_kernel<<<NTOT/4, 256>>>(pc0, w2_1,b2_1, w2_2,b2_2, w2_3,b2_3, w3_1);
    conv3_kernel<<<NTOT/2, 256>>>(pc0, w3_1,b3_1, w3_2,b3_2, w3_3,b3_3, wfc,bfc, out);
}

// round 16
// speedup vs baseline: 1.1123x; 1.0067x over previous
#include <cuda_runtime.h>
#include <cuda_bf16.h>
#include <math.h>
#include <stdint.h>

#define BB 2
#define NNPTS 4096
#define CF 64
#define KNN 32
#define NTOT (BB*NNPTS)

// ---------------- scratch (static __device__, no allocs) ----------------
__device__ float  g_K[(size_t)BB*NNPTS*NNPTS];     // 128 MB transport kernel
__device__ unsigned short g_a16[(size_t)NTOT*192]; // split-bf16 A rows [hi|hi|lo]
__device__ unsigned short g_b16[(size_t)NTOT*192]; // split-bf16 B rows [hi|lo|hi]
__device__ float  g_n0[NTOT];
__device__ float  g_n1[NTOT];
__device__ float4 g_pts0[NTOT];
__device__ float  g_colsum[NTOT];
__device__ float4 g_w4t[NTOT];
__device__ float  g_otflow[NTOT*3];
__device__ int    g_idx[NTOT*KNN];
__device__ float  g_y2[NTOT*64];
__device__ float  g_y3[NTOT*128];

__device__ __forceinline__ float lrelu(float x){ return (x > 0.f) ? x : 0.1f*x; }

__device__ __forceinline__ uint32_t smem_u32(const void* p) {
    uint32_t a;
    asm("{ .reg .u64 t; cvta.to.shared.u64 t, %1; cvt.u32.u64 %0, t; }" : "=r"(a) : "l"(p));
    return a;
}

// ---------------- prep 1: point norms + packed pts + colsum zero ---------
__global__ __launch_bounds__(256)
void prep_norm_kernel(const float* __restrict__ pc0, const float* __restrict__ pc1)
{
    int i = blockIdx.x*blockDim.x + threadIdx.x;
    if (i >= 2*NTOT) return;
    int which = i / NTOT, row = i % NTOT;
    const float* pc = which ? pc1 : pc0;
    float x = pc[row*3+0], y = pc[row*3+1], z = pc[row*3+2];
    float n2 = x*x + y*y + z*z;
    if (which) g_n1[row] = n2;
    else {
        g_n0[row] = n2; g_colsum[row] = 0.f;
        g_pts0[row] = make_float4(x, y, z, n2);
    }
}

// ---- prep 2: normalize + split-bf16 row-major images --------------------
__global__ __launch_bounds__(256)
void prep_feat_kernel(const float* __restrict__ f0, const float* __restrict__ f1)
{
    int w    = (blockIdx.x*blockDim.x + threadIdx.x) >> 5;
    int lane = threadIdx.x & 31;
    if (w >= 2*NTOT) return;
    int which = w / NTOT;
    int row   = w % NTOT;
    const float* f = which ? f1 : f0;
    float v0 = f[row*CF + lane];
    float v1 = f[row*CF + 32 + lane];
    float ss = v0*v0 + v1*v1;
    #pragma unroll
    for (int o = 16; o > 0; o >>= 1) ss += __shfl_xor_sync(0xffffffffu, ss, o);
    float inv = rsqrtf(ss + 1e-8f);
    v0 *= inv; v1 *= inv;

    unsigned short* base = (which ? g_b16 : g_a16) + (size_t)row*192;
    #pragma unroll
    for (int t = 0; t < 2; t++) {
        int c = lane + t*32;
        float v = t ? v1 : v0;
        __nv_bfloat16 h = __float2bfloat16(v);
        unsigned short hb = __bfloat16_as_ushort(h);
        unsigned short lb = __bfloat16_as_ushort(__float2bfloat16(v - __bfloat162float(h)));
        if (!which) { base[c] = hb; base[64+c] = hb; base[128+c] = lb; }   // A: hi|hi|lo
        else        { base[c] = hb; base[64+c] = lb; base[128+c] = hb; }   // B: hi|lo|hi
    }
}

// ---------------- KNN: radix-select 32 smallest sqdists per row ----------
__global__ __launch_bounds__(256)
void knn_kernel()
{
    int n = blockIdx.x; int b = n / NNPTS;
    const float4* pts = g_pts0 + b*NNPTS;
    int tid = threadIdx.x;
    int lane = tid & 31;
    float4 q = g_pts0[n];
    unsigned key[16];
    #pragma unroll
    for (int i = 0; i < 16; i++) {
        float4 p = pts[tid + i*256];
        float dot = fmaf(p.x, q.x, fmaf(p.y, q.y, p.z*q.z));
        float d = q.w + p.w - 2.0f*dot;
        unsigned u = __float_as_uint(d);
        u = (u & 0x80000000u) ? ~u : (u | 0x80000000u);
        key[i] = u;
    }
    __shared__ int hist[256];
    __shared__ unsigned s_prefix;
    __shared__ int s_krem, s_cl, s_ct;
    __shared__ int s_out[KNN];
    __shared__ int s_tie[64];
    if (tid == 0) { s_prefix = 0u; s_krem = KNN; s_cl = 0; s_ct = 0; }
    for (int r = 0; r < 4; r++) {
        int shift = 24 - 8*r;
        hist[tid] = 0;
        __syncthreads();
        unsigned pref = s_prefix;
        unsigned msk  = (r == 0) ? 0u : (0xFFFFFFFFu << (32 - 8*r));
        #pragma unroll
        for (int i = 0; i < 16; i++)
            if ((key[i] & msk) == (pref & msk))
                atomicAdd(&hist[(key[i] >> shift) & 255], 1);
        __syncthreads();
        if (tid < 32) {
            int krem = s_krem;
            int loc[8]; int tot = 0;
            #pragma unroll
            for (int j = 0; j < 8; j++) { loc[j] = hist[tid*8 + j]; tot += loc[j]; }
            int incl = tot;
            #pragma unroll
            for (int o = 1; o < 32; o <<= 1) {
                int x = __shfl_up_sync(0xffffffffu, incl, o);
                if (lane >= o) incl += x;
            }
            int excl = incl - tot;
            if (excl < krem && krem <= incl) {
                int rem = krem - excl;
                int d = 0;
                #pragma unroll
                for (int j = 0; j < 7; j++) if (rem > loc[d]) { rem -= loc[d]; d++; }
                s_prefix = pref | ((unsigned)(tid*8 + d) << shift);
                s_krem = rem;
            }
        }
        __syncthreads();
    }
    unsigned pivot = s_prefix;
    #pragma unroll
    for (int i = 0; i < 16; i++) {
        unsigned u = key[i];
        if (u < pivot)       { int p = atomicAdd(&s_cl, 1); s_out[p] = tid + i*256; }
        else if (u == pivot) { int t = atomicAdd(&s_ct, 1); if (t < 64) s_tie[t] = tid + i*256; }
    }
    __syncthreads();
    if (tid == 0) {
        int cl = s_cl;
        int nt = (s_ct < 64) ? s_ct : 64;
        int need = KNN - cl;
        for (int s = 0; s < need; s++) {
            int best = 0x7FFFFFFF, bi = 0;
            for (int t = 0; t < nt; t++) if (s_tie[t] < best) { best = s_tie[t]; bi = t; }
            s_tie[bi] = 0x7FFFFFFF;
            s_out[cl + s] = best;
        }
    }
    __syncthreads();
    if (tid < KNN) g_idx[n*KNN + tid] = s_out[tid];
}

// ------- kmat: bf16 split GEMM via mma.sync m16n8k16 + ldmatrix ----------
// Tile 128x64, 8 warps (4 row x 2 col), each warp 32x32 (2x4 mma tiles).
// smem: A 128x200 bf16 (51200 B), B 64x200 bf16 (25600), P/N arrays, D reuse A.
__device__ __forceinline__ void mma16816(float* d, const uint32_t* a, const uint32_t* b)
{
    asm volatile(
        "mma.sync.aligned.m16n8k16.row.col.f32.bf16.bf16.f32 "
        "{%0,%1,%2,%3}, {%4,%5,%6,%7}, {%8,%9}, {%0,%1,%2,%3};"
        : "+f"(d[0]), "+f"(d[1]), "+f"(d[2]), "+f"(d[3])
        : "r"(a[0]), "r"(a[1]), "r"(a[2]), "r"(a[3]), "r"(b[0]), "r"(b[1]));
}
__device__ __forceinline__ void ldm_x4(uint32_t* d, uint32_t addr)
{
    asm volatile("ldmatrix.sync.aligned.m8n8.x4.shared.b16 {%0,%1,%2,%3}, [%4];"
        : "=r"(d[0]), "=r"(d[1]), "=r"(d[2]), "=r"(d[3]) : "r"(addr));
}

__global__ __launch_bounds__(256, 2)
void kmat_kernel(const float* __restrict__ pc0, const float* __restrict__ pc1,
                 const float* __restrict__ epsilon)
{
    extern __shared__ char smem[];
    float* P0  = (float*)(smem + 76800);   // 3*128
    float* P1  = (float*)(smem + 78336);   // 3*64
    float* N0s = (float*)(smem + 79104);   // 128
    float* N1s = (float*)(smem + 79616);   // 64

    int tid = threadIdx.x, wid = tid >> 5, lane = tid & 31;
    int g = lane >> 2, t = lane & 3;
    int bz = blockIdx.z;
    int row0 = blockIdx.y*128, col0 = blockIdx.x*64;

    {   // A copy: 128 rows x 384 B (row-major gmem -> stride-400 smem)
        const char* src = (const char*)(g_a16 + ((size_t)(bz*NNPTS) + row0)*192);
        #pragma unroll
        for (int i = 0; i < 12; i++) {
            int idx = tid + i*256;               // 0..3071 float4 slots
            int row = idx / 24, j = idx - row*24;
            float4 v = *(const float4*)(src + row*384 + j*16);
            *(float4*)(smem + row*400 + j*16) = v;
        }
        const char* srcb = (const char*)(g_b16 + ((size_t)(bz*NNPTS) + col0)*192);
        #pragma unroll
        for (int i = 0; i < 6; i++) {
            int idx = tid + i*256;               // 0..1535
            int row = idx / 24, j = idx - row*24;
            float4 v = *(const float4*)(srcb + row*384 + j*16);
            *(float4*)(smem + 51200 + row*400 + j*16) = v;
        }
    }
    if (tid < 128) {
        int r = tid;
        #pragma unroll
        for (int d = 0; d < 3; d++) P0[d*128 + r] = pc0[(bz*NNPTS+row0+r)*3 + d];
        N0s[r] = g_n0[bz*NNPTS + row0 + r];
    } else if (tid < 192) {
        int r = tid - 128;
        #pragma unroll
        for (int d = 0; d < 3; d++) P1[d*64 + r] = pc1[(bz*NNPTS+col0+r)*3 + d];
        N1s[r] = g_n1[bz*NNPTS + col0 + r];
    }
    __syncthreads();

    int wr = wid >> 1, wc = wid & 1;
    float acc[2][4][4];
    #pragma unroll
    for (int mi = 0; mi < 2; mi++)
        #pragma unroll
        for (int ni = 0; ni < 4; ni++)
            acc[mi][ni][0]=acc[mi][ni][1]=acc[mi][ni][2]=acc[mi][ni][3]=0.f;

    uint32_t sb = smem_u32(smem);
    // ldmatrix lane->row addressing: matrix m = lane>>3, within-row = lane&7
    // A tiles (per mi): m0=(rows+0,k0) m1=(rows+8,k0) m2=(rows+0,k0+8) m3=(rows+8,k0+8)
    uint32_t aOff = (uint32_t)((wr*32 + ((lane>>3)&1)*8 + (lane&7))*400 + (lane>>4)*16);
    // B tiles (per call c covering ni=2c,2c+1): m0=(n+0,k0) m1=(n+0,k0+8) m2=(n+8,k0) m3=(n+8,k0+8)
    uint32_t bOff = 51200u + (uint32_t)((wc*32 + (lane>>4)*8 + (lane&7))*400 + ((lane>>3)&1)*16);

    #pragma unroll 2
    for (int k0 = 0; k0 < 192; k0 += 16) {
        uint32_t a[2][4];
        ldm_x4(a[0], sb + aOff + k0*2);
        ldm_x4(a[1], sb + aOff + 16*400 + k0*2);
        uint32_t bfr[2][4];
        ldm_x4(bfr[0], sb + bOff + k0*2);
        ldm_x4(bfr[1], sb + bOff + 16*400 + k0*2);
        #pragma unroll
        for (int mi = 0; mi < 2; mi++)
            #pragma unroll
            for (int ni = 0; ni < 4; ni++) {
                uint32_t bb[2] = { bfr[ni>>1][(ni&1)*2], bfr[ni>>1][(ni&1)*2 + 1] };
                mma16816(acc[mi][ni], a[mi], bb);
            }
    }
    __syncthreads();                         // done reading A/B; reuse A as D

    float* D = (float*)smem;                 // [128][65]
    {
        float eps = __expf(epsilon[0]) + 0.025f;
        float inv_eps = 1.0f/eps;
        #pragma unroll
        for (int mi = 0; mi < 2; mi++) {
            int rA = wr*32 + mi*16 + g;
            #pragma unroll
            for (int half = 0; half < 2; half++) {
                int r = rA + half*8;
                float p0x = P0[r], p0y = P0[128+r], p0z = P0[256+r];
                float n0v = N0s[r];
                #pragma unroll
                for (int ni = 0; ni < 4; ni++) {
                    #pragma unroll
                    for (int cc = 0; cc < 2; cc++) {
                        int c = wc*32 + ni*8 + t*2 + cc;
                        float dot = acc[mi][ni][half*2 + cc];
                        float pd  = fmaf(p0x, P1[c], fmaf(p0y, P1[64+c], p0z*P1[128+c]));
                        float sqd = n0v + N1s[c] - 2.0f*pd;
                        D[r*65 + c] = (sqd < 100.0f) ? __expf((dot - 1.0f)*inv_eps) : 0.0f;
                    }
                }
            }
        }
    }
    __syncthreads();
    {   // coalesced store of D tile (128x64)
        #pragma unroll
        for (int it = 0; it < 8; it++) {
            int idx = tid + it*256;
            int row = idx >> 4, c4 = (idx & 15)*4;
            const float* s = D + row*65 + c4;
            float4 v = make_float4(s[0], s[1], s[2], s[3]);
            *(float4*)&g_K[((size_t)(bz*NNPTS) + row0 + row)*NNPTS + col0 + c4] = v;
        }
    }
    if (tid < 64) {                          // column sums of this tile
        float s = 0.f;
        #pragma unroll 8
        for (int r = 0; r < 128; r++) s += D[r*65 + tid];
        atomicAdd(&g_colsum[bz*NNPTS + col0 + tid], s);
    }
}

// -------- b vector, stored transposed for rowpass ------------------------
__global__ __launch_bounds__(256)
void bvec_kernel(const float* __restrict__ pc1,
                 const float* __restrict__ gamma, const float* __restrict__ epsilon)
{
    int i = blockIdx.x*blockDim.x + threadIdx.x;
    if (i >= NTOT) return;
    float eps = expf(epsilon[0]) + 0.025f;
    float gam = expf(gamma[0]);
    float power = gam/(gam+eps);
    float kta = g_colsum[i] * (1.0f/NNPTS);
    float b = powf((1.0f/NNPTS)/(kta + 1e-8f), power);
    int bz = i / NNPTS, c = i % NNPTS;
    g_w4t[bz*NNPTS + (c & 3)*1024 + (c >> 2)] =
        make_float4(b, b*pc1[i*3+0], b*pc1[i*3+1], b*pc1[i*3+2]);
}

// ---------------- row pass: Kb, K b pc1 -> ot_flow ------------------------
__global__ __launch_bounds__(256)
void rowpass_kernel(const float* __restrict__ pc0,
                    const float* __restrict__ gamma, const float* __restrict__ epsilon)
{
    __shared__ float rbuf[8][4][4];
    int tid = threadIdx.x;
    int r0 = blockIdx.x * 4;
    int bz = r0 / NNPTS;
    const float4* wt = g_w4t + bz*NNPTS;
    int wid = tid >> 5, lane = tid & 31;

    const float4* K0 = (const float4*)(g_K + (size_t)(r0+0)*NNPTS);
    const float4* K1 = (const float4*)(g_K + (size_t)(r0+1)*NNPTS);
    const float4* K2 = (const float4*)(g_K + (size_t)(r0+2)*NNPTS);
    const float4* K3 = (const float4*)(g_K + (size_t)(r0+3)*NNPTS);
    float acc[4][4];
    #pragma unroll
    for (int r = 0; r < 4; r++)
        acc[r][0]=acc[r][1]=acc[r][2]=acc[r][3]=0.f;
    #pragma unroll
    for (int i = 0; i < 4; i++) {
        int f = tid + i*256;
        float4 w0 = __ldg(&wt[f]),      w1 = __ldg(&wt[1024+f]);
        float4 w2 = __ldg(&wt[2048+f]), w3 = __ldg(&wt[3072+f]);
        float4 kr[4] = { K0[f], K1[f], K2[f], K3[f] };
        #pragma unroll
        for (int r = 0; r < 4; r++) {
            float4 k = kr[r];
            acc[r][0] = fmaf(k.x,w0.x, fmaf(k.y,w1.x, fmaf(k.z,w2.x, fmaf(k.w,w3.x, acc[r][0]))));
            acc[r][1] = fmaf(k.x,w0.y, fmaf(k.y,w1.y, fmaf(k.z,w2.y, fmaf(k.w,w3.y, acc[r][1]))));
            acc[r][2] = fmaf(k.x,w0.z, fmaf(k.y,w1.z, fmaf(k.z,w2.z, fmaf(k.w,w3.z, acc[r][2]))));
            acc[r][3] = fmaf(k.x,w0.w, fmaf(k.y,w1.w, fmaf(k.z,w2.w, fmaf(k.w,w3.w, acc[r][3]))));
        }
    }
    #pragma unroll
    for (int r = 0; r < 4; r++) {
        #pragma unroll
        for (int o = 16; o > 0; o >>= 1) {
            acc[r][0] += __shfl_xor_sync(0xffffffffu, acc[r][0], o);
            acc[r][1] += __shfl_xor_sync(0xffffffffu, acc[r][1], o);
            acc[r][2] += __shfl_xor_sync(0xffffffffu, acc[r][2], o);
            acc[r][3] += __shfl_xor_sync(0xffffffffu, acc[r][3], o);
        }
        if (lane == 0) {
            rbuf[wid][r][0]=acc[r][0]; rbuf[wid][r][1]=acc[r][1];
            rbuf[wid][r][2]=acc[r][2]; rbuf[wid][r][3]=acc[r][3];
        }
    }
    __syncthreads();
    if (tid < 4) {
        int r = tid;
        float Kb=0.f,Sx=0.f,Sy=0.f,Sz=0.f;
        #pragma unroll
        for (int w = 0; w < 8; w++) {
            Kb += rbuf[w][r][0]; Sx += rbuf[w][r][1];
            Sy += rbuf[w][r][2]; Sz += rbuf[w][r][3];
        }
        float eps = expf(epsilon[0]) + 0.025f;
        float gam = expf(gamma[0]);
        float power = gam/(gam+eps);
        float a  = powf((1.0f/NNPTS)/(Kb + 1e-8f), power);
        float rs = a*Kb;
        float inv = 1.0f/(rs + 1e-8f);
        int row = r0 + r;
        g_otflow[row*3+0] = a*Sx*inv - pc0[row*3+0];
        g_otflow[row*3+1] = a*Sy*inv - pc0[row*3+1];
        g_otflow[row*3+2] = a*Sz*inv - pc0[row*3+2];
    }
}

// ---------------- conv1: edge conv (6->32->32->32) + y2 epilogue ---------
__global__ __launch_bounds__(256)
void conv1_kernel(const float* __restrict__ pc0,
                  const float* __restrict__ W1, const float* __restrict__ B1,
                  const float* __restrict__ W2, const float* __restrict__ B2,
                  const float* __restrict__ W3, const float* __restrict__ B3,
                  const float* __restrict__ W2a)
{
    __shared__ __align__(16) float in_s[8][KNN][8];
    __shared__ float h[8][32];
    __shared__ float h2[8][32];
    __shared__ int   nb_s[8][KNN];

    int tid = threadIdx.x;
    int g = tid >> 5, c = tid & 31;
    int node = blockIdx.x*8 + g;
    int b = node / NNPTS;

    nb_s[g][c] = g_idx[node*KNN + c];
    __syncthreads();

    for (int e = c; e < KNN*6; e += 32) {
        int j = e / 6, k = e % 6;
        int nb = nb_s[g][j];
        float v;
        if (k < 3) v = g_otflow[(b*NNPTS + nb)*3 + k];
        else       v = pc0[(b*NNPTS + nb)*3 + (k-3)] - pc0[node*3 + (k-3)];
        in_s[g][j][k] = v;
    }
    __syncthreads();

    float acc[KNN];
    float bias1 = B1[c];
    #pragma unroll
    for (int j = 0; j < KNN; j++) acc[j] = bias1;
    #pragma unroll
    for (int k = 0; k < 6; k++) {
        float w = W1[k*32 + c];
        #pragma unroll
        for (int j = 0; j < KNN; j++) acc[j] = fmaf(in_s[g][j][k], w, acc[j]);
    }
    float mx = -3.4e38f;
    #pragma unroll
    for (int j = 0; j < KNN; j++) mx = fmaxf(mx, lrelu(acc[j]));
    h[g][c] = mx;
    __syncthreads();

    float a2 = B2[c];
    for (int k = 0; k < 32; k++) a2 = fmaf(h[g][k], W2[k*32 + c], a2);
    h2[g][c] = lrelu(a2);
    __syncthreads();

    float a3 = B3[c];
    for (int k = 0; k < 32; k++) a3 = fmaf(h2[g][k], W3[k*32 + c], a3);
    h[g][c] = lrelu(a3);
    __syncthreads();

    #pragma unroll
    for (int t = 0; t < 2; t++) {
        int cc = c + t*32;
        float y = 0.f;
        for (int k = 0; k < 32; k++) y = fmaf(h[g][k], W2a[k*64 + cc], y);
        g_y2[(size_t)node*64 + cc] = y;
    }
}

// ---------------- conv2: gather y2 + edge -> 64, dense x2, y3 epi --------
__global__ __launch_bounds__(256)
void conv2_kernel(const float* __restrict__ pc0,
                  const float* __restrict__ W1, const float* __restrict__ B1,
                  const float* __restrict__ W2, const float* __restrict__ B2,
                  const float* __restrict__ W3, const float* __restrict__ B3,
                  const float* __restrict__ W3a)
{
    __shared__ int    nb_s[4][KNN];
    __shared__ float4 es[4][KNN];
    __shared__ float  h[4][64];
    __shared__ float  h2[4][64];

    int tid = threadIdx.x;
    int g = tid >> 6, c = tid & 63;
    int node = blockIdx.x*4 + g;
    int b = node / NNPTS;

    if (c < KNN) {
        int nb = g_idx[node*KNN + c];
        nb_s[g][c] = nb;
        es[g][c] = make_float4(pc0[(b*NNPTS+nb)*3+0] - pc0[node*3+0],
                               pc0[(b*NNPTS+nb)*3+1] - pc0[node*3+1],
                               pc0[(b*NNPTS+nb)*3+2] - pc0[node*3+2], 0.f);
    }
    __syncthreads();

    const float* yb = g_y2 + (size_t)b*NNPTS*64;
    float yv[KNN];
    #pragma unroll
    for (int j = 0; j < KNN; j++) yv[j] = yb[nb_s[g][j]*64 + c];

    float wb0 = W1[32*64 + c], wb1 = W1[33*64 + c], wb2 = W1[34*64 + c];
    float bias = B1[c];
    float mx = -3.4e38f;
    #pragma unroll
    for (int j = 0; j < KNN; j++) {
        float4 e = es[g][j];
        float a = yv[j] + fmaf(e.x, wb0, fmaf(e.y, wb1, fmaf(e.z, wb2, bias)));
        mx = fmaxf(mx, lrelu(a));
    }
    h[g][c] = mx;
    __syncthreads();

    float a2 = B2[c];
    for (int k = 0; k < 64; k++) a2 = fmaf(h[g][k], W2[k*64 + c], a2);
    h2[g][c] = lrelu(a2);
    __syncthreads();

    float a3 = B3[c];
    for (int k = 0; k < 64; k++) a3 = fmaf(h2[g][k], W3[k*64 + c], a3);
    h[g][c] = lrelu(a3);
    __syncthreads();

    #pragma unroll
    for (int t = 0; t < 2; t++) {
        int cc = c + t*64;
        float y = 0.f;
        for (int k = 0; k < 64; k++) y = fmaf(h[g][k], W3a[k*128 + cc], y);
        g_y3[(size_t)node*128 + cc] = y;
    }
}

// ---------------- conv3: gather y3 + edge -> 128, dense, fc, residual ----
__global__ __launch_bounds__(256)
void conv3_kernel(const float* __restrict__ pc0,
                  const float* __restrict__ W1, const float* __restrict__ B1,
                  const float* __restrict__ W2, const float* __restrict__ B2,
                  const float* __restrict__ W3, const float* __restrict__ B3,
                  const float* __restrict__ Wfc, const float* __restrict__ Bfc,
                  float* __restrict__ dout)
{
    __shared__ int    nb_s[2][KNN];
    __shared__ float4 es[2][KNN];
    __shared__ float  h[2][128];
    __shared__ float  h2[2][128];

    int tid = threadIdx.x;
    int g = tid >> 7, c = tid & 127;
    int node = blockIdx.x*2 + g;
    int b = node / NNPTS;

    if (c < KNN) {
        int nb = g_idx[node*KNN + c];
        nb_s[g][c] = nb;
        es[g][c] = make_float4(pc0[(b*NNPTS+nb)*3+0] - pc0[node*3+0],
                               pc0[(b*NNPTS+nb)*3+1] - pc0[node*3+1],
                               pc0[(b*NNPTS+nb)*3+2] - pc0[node*3+2], 0.f);
    }
    __syncthreads();

    const float* yb = g_y3 + (size_t)b*NNPTS*128;
    float yv[KNN];
    #pragma unroll
    for (int j = 0; j < KNN; j++) yv[j] = yb[nb_s[g][j]*128 + c];

    float wb0 = W1[64*128 + c], wb1 = W1[65*128 + c], wb2 = W1[66*128 + c];
    float bias = B1[c];
    float mx = -3.4e38f;
    #pragma unroll
    for (int j = 0; j < KNN; j++) {
        float4 e = es[g][j];
        float a = yv[j] + fmaf(e.x, wb0, fmaf(e.y, wb1, fmaf(e.z, wb2, bias)));
        mx = fmaxf(mx, lrelu(a));
    }
    h[g][c] = mx;
    __syncthreads();

    float a2 = B2[c];
    for (int k = 0; k < 128; k++) a2 = fmaf(h[g][k], W2[k*128 + c], a2);
    h2[g][c] = lrelu(a2);
    __syncthreads();

    float a3 = B3[c];
    for (int k = 0; k < 128; k++) a3 = fmaf(h2[g][k], W3[k*128 + c], a3);
    h[g][c] = lrelu(a3);
    __syncthreads();

    if (c < 3) {
        float o = Bfc[c];
        for (int k = 0; k < 128; k++) o = fmaf(h[g][k], Wfc[k*3 + c], o);
        dout[node*3 + c] = g_otflow[node*3 + c] + o;
    }
}

// ---------------- launch --------------------------------------------------
extern "C" void kernel_launch(void* const* d_in, const int* in_sizes, int n_in,
                              void* d_out, int out_size)
{
    const float* pc0   = (const float*)d_in[0];
    const float* pc1   = (const float*)d_in[1];
    const float* f0    = (const float*)d_in[2];
    const float* f1    = (const float*)d_in[3];
    const float* gamma = (const float*)d_in[4];
    const float* eps   = (const float*)d_in[5];
    const float* w1_1=(const float*)d_in[6],  *b1_1=(const float*)d_in[7];
    const float* w1_2=(const float*)d_in[8],  *b1_2=(const float*)d_in[9];
    const float* w1_3=(const float*)d_in[10], *b1_3=(const float*)d_in[11];
    const float* w2_1=(const float*)d_in[12], *b2_1=(const float*)d_in[13];
    const float* w2_2=(const float*)d_in[14], *b2_2=(const float*)d_in[15];
    const float* w2_3=(const float*)d_in[16], *b2_3=(const float*)d_in[17];
    const float* w3_1=(const float*)d_in[18], *b3_1=(const float*)d_in[19];
    const float* w3_2=(const float*)d_in[20], *b3_2=(const float*)d_in[21];
    const float* w3_3=(const float*)d_in[22], *b3_3=(const float*)d_in[23];
    const float* wfc =(const float*)d_in[24], *bfc =(const float*)d_in[25];
    float* out = (float*)d_out;

    cudaFuncSetAttribute(kmat_kernel, cudaFuncAttributeMaxDynamicSharedMemorySize, 80896);

    prep_norm_kernel<<<(2*NTOT + 255)/256, 256>>>(pc0, pc1);      // 1
    knn_kernel<<<NTOT, 256>>>();                                   // 2
    prep_feat_kernel<<<2048, 256>>>(f0, f1);                       // 3
    kmat_kernel<<<dim3(NNPTS/64, NNPTS/128, BB), 256, 79872>>>(pc0, pc1, eps); // 4 = ncu slot
    bvec_kernel<<<(NTOT + 255)/256, 256>>>(pc1, gamma, eps);
    rowpass_kernel<<<NTOT/4, 256>>>(pc0, gamma, eps);
    conv1_kernel<<<NTOT/8, 256>>>(pc0, w1_1,b1_1, w1_2,b1_2, w1_3,b1_3, w2_1);
    conv2_kernel<<<NTOT/4, 256>>>(pc0, w2_1,b2_1, w2_2,b2_2, w2_3,b2_3, w3_1);
    conv3_kernel<<<NTOT/2, 256>>>(pc0, w3_1,b3_1, w3_2,b3_2, w3_3,b3_3, wfc,bfc, out);
}

// round 17
// speedup vs baseline: 1.2756x; 1.1468x over previous
#include <cuda_runtime.h>
#include <cuda_bf16.h>
#include <math.h>
#include <stdint.h>

#define BB 2
#define NNPTS 4096
#define CF 64
#define KNN 32
#define NTOT (BB*NNPTS)

// ---------------- scratch (static __device__, no allocs) ----------------
__device__ unsigned short g_K16[(size_t)BB*NNPTS*NNPTS]; // 64 MB bf16 transport kernel
__device__ unsigned short g_a16[(size_t)NTOT*192]; // split-bf16 A rows [hi|hi|lo]
__device__ unsigned short g_b16[(size_t)NTOT*192]; // split-bf16 B rows [hi|lo|hi]
__device__ float  g_n0[NTOT];
__device__ float  g_n1[NTOT];
__device__ float4 g_pts0[NTOT];
__device__ float  g_colsum[NTOT];
__device__ float4 g_w4t[NTOT];
__device__ float  g_otflow[NTOT*3];
__device__ int    g_idx[NTOT*KNN];
__device__ float  g_y2[NTOT*64];
__device__ float  g_y3[NTOT*128];

__device__ __forceinline__ float lrelu(float x){ return (x > 0.f) ? x : 0.1f*x; }

__device__ __forceinline__ uint32_t smem_u32(const void* p) {
    uint32_t a;
    asm("{ .reg .u64 t; cvta.to.shared.u64 t, %1; cvt.u32.u64 %0, t; }" : "=r"(a) : "l"(p));
    return a;
}

// ---------------- prep 1: point norms + packed pts + colsum zero ---------
__global__ __launch_bounds__(256)
void prep_norm_kernel(const float* __restrict__ pc0, const float* __restrict__ pc1)
{
    int i = blockIdx.x*blockDim.x + threadIdx.x;
    if (i >= 2*NTOT) return;
    int which = i / NTOT, row = i % NTOT;
    const float* pc = which ? pc1 : pc0;
    float x = pc[row*3+0], y = pc[row*3+1], z = pc[row*3+2];
    float n2 = x*x + y*y + z*z;
    if (which) g_n1[row] = n2;
    else {
        g_n0[row] = n2; g_colsum[row] = 0.f;
        g_pts0[row] = make_float4(x, y, z, n2);
    }
}

// ---- prep 2: normalize + split-bf16 row-major images --------------------
__global__ __launch_bounds__(256)
void prep_feat_kernel(const float* __restrict__ f0, const float* __restrict__ f1)
{
    int w    = (blockIdx.x*blockDim.x + threadIdx.x) >> 5;
    int lane = threadIdx.x & 31;
    if (w >= 2*NTOT) return;
    int which = w / NTOT;
    int row   = w % NTOT;
    const float* f = which ? f1 : f0;
    float v0 = f[row*CF + lane];
    float v1 = f[row*CF + 32 + lane];
    float ss = v0*v0 + v1*v1;
    #pragma unroll
    for (int o = 16; o > 0; o >>= 1) ss += __shfl_xor_sync(0xffffffffu, ss, o);
    float inv = rsqrtf(ss + 1e-8f);
    v0 *= inv; v1 *= inv;

    unsigned short* base = (which ? g_b16 : g_a16) + (size_t)row*192;
    #pragma unroll
    for (int t = 0; t < 2; t++) {
        int c = lane + t*32;
        float v = t ? v1 : v0;
        __nv_bfloat16 h = __float2bfloat16(v);
        unsigned short hb = __bfloat16_as_ushort(h);
        unsigned short lb = __bfloat16_as_ushort(__float2bfloat16(v - __bfloat162float(h)));
        if (!which) { base[c] = hb; base[64+c] = hb; base[128+c] = lb; }   // A: hi|hi|lo
        else        { base[c] = hb; base[64+c] = lb; base[128+c] = hb; }   // B: hi|lo|hi
    }
}

// ---------------- KNN: radix-select 32 smallest sqdists per row ----------
__global__ __launch_bounds__(256)
void knn_kernel()
{
    int n = blockIdx.x; int b = n / NNPTS;
    const float4* pts = g_pts0 + b*NNPTS;
    int tid = threadIdx.x;
    int lane = tid & 31;
    float4 q = g_pts0[n];
    unsigned key[16];
    #pragma unroll
    for (int i = 0; i < 16; i++) {
        float4 p = pts[tid + i*256];
        float dot = fmaf(p.x, q.x, fmaf(p.y, q.y, p.z*q.z));
        float d = q.w + p.w - 2.0f*dot;
        unsigned u = __float_as_uint(d);
        u = (u & 0x80000000u) ? ~u : (u | 0x80000000u);
        key[i] = u;
    }
    __shared__ int hist[256];
    __shared__ unsigned s_prefix;
    __shared__ int s_krem, s_cl, s_ct;
    __shared__ int s_out[KNN];
    __shared__ int s_tie[64];
    if (tid == 0) { s_prefix = 0u; s_krem = KNN; s_cl = 0; s_ct = 0; }
    for (int r = 0; r < 4; r++) {
        int shift = 24 - 8*r;
        hist[tid] = 0;
        __syncthreads();
        unsigned pref = s_prefix;
        unsigned msk  = (r == 0) ? 0u : (0xFFFFFFFFu << (32 - 8*r));
        #pragma unroll
        for (int i = 0; i < 16; i++)
            if ((key[i] & msk) == (pref & msk))
                atomicAdd(&hist[(key[i] >> shift) & 255], 1);
        __syncthreads();
        if (tid < 32) {
            int krem = s_krem;
            int loc[8]; int tot = 0;
            #pragma unroll
            for (int j = 0; j < 8; j++) { loc[j] = hist[tid*8 + j]; tot += loc[j]; }
            int incl = tot;
            #pragma unroll
            for (int o = 1; o < 32; o <<= 1) {
                int x = __shfl_up_sync(0xffffffffu, incl, o);
                if (lane >= o) incl += x;
            }
            int excl = incl - tot;
            if (excl < krem && krem <= incl) {
                int rem = krem - excl;
                int d = 0;
                #pragma unroll
                for (int j = 0; j < 7; j++) if (rem > loc[d]) { rem -= loc[d]; d++; }
                s_prefix = pref | ((unsigned)(tid*8 + d) << shift);
                s_krem = rem;
            }
        }
        __syncthreads();
    }
    unsigned pivot = s_prefix;
    #pragma unroll
    for (int i = 0; i < 16; i++) {
        unsigned u = key[i];
        if (u < pivot)       { int p = atomicAdd(&s_cl, 1); s_out[p] = tid + i*256; }
        else if (u == pivot) { int t = atomicAdd(&s_ct, 1); if (t < 64) s_tie[t] = tid + i*256; }
    }
    __syncthreads();
    if (tid == 0) {
        int cl = s_cl;
        int nt = (s_ct < 64) ? s_ct : 64;
        int need = KNN - cl;
        for (int s = 0; s < need; s++) {
            int best = 0x7FFFFFFF, bi = 0;
            for (int t = 0; t < nt; t++) if (s_tie[t] < best) { best = s_tie[t]; bi = t; }
            s_tie[bi] = 0x7FFFFFFF;
            s_out[cl + s] = best;
        }
    }
    __syncthreads();
    if (tid < KNN) g_idx[n*KNN + tid] = s_out[tid];
}

// ------- kmat: bf16 split GEMM via mma.sync m16n8k16 + ldmatrix ----------
// Tile 128x64, 8 warps (4 row x 2 col), each warp 32x32 (2x4 mma tiles).
// D staged as bf16 (stride 144 B) -> coalesced uint4 store; fused colsum.
__device__ __forceinline__ void mma16816(float* d, const uint32_t* a, const uint32_t* b)
{
    asm volatile(
        "mma.sync.aligned.m16n8k16.row.col.f32.bf16.bf16.f32 "
        "{%0,%1,%2,%3}, {%4,%5,%6,%7}, {%8,%9}, {%0,%1,%2,%3};"
        : "+f"(d[0]), "+f"(d[1]), "+f"(d[2]), "+f"(d[3])
        : "r"(a[0]), "r"(a[1]), "r"(a[2]), "r"(a[3]), "r"(b[0]), "r"(b[1]));
}
__device__ __forceinline__ void ldm_x4(uint32_t* d, uint32_t addr)
{
    asm volatile("ldmatrix.sync.aligned.m8n8.x4.shared.b16 {%0,%1,%2,%3}, [%4];"
        : "=r"(d[0]), "=r"(d[1]), "=r"(d[2]), "=r"(d[3]) : "r"(addr));
}

__global__ __launch_bounds__(256, 2)
void kmat_kernel(const float* __restrict__ pc0, const float* __restrict__ pc1,
                 const float* __restrict__ epsilon)
{
    extern __shared__ char smem[];
    float* P0  = (float*)(smem + 76800);   // 3*128
    float* P1  = (float*)(smem + 78336);   // 3*64
    float* N0s = (float*)(smem + 79104);   // 128
    float* N1s = (float*)(smem + 79616);   // 64

    int tid = threadIdx.x, wid = tid >> 5, lane = tid & 31;
    int g = lane >> 2, t = lane & 3;
    int bz = blockIdx.z;
    int row0 = blockIdx.y*128, col0 = blockIdx.x*64;

    {   // A copy: 128 rows x 384 B (row-major gmem -> stride-400 smem)
        const char* src = (const char*)(g_a16 + ((size_t)(bz*NNPTS) + row0)*192);
        #pragma unroll
        for (int i = 0; i < 12; i++) {
            int idx = tid + i*256;               // 0..3071 float4 slots
            int row = idx / 24, j = idx - row*24;
            float4 v = *(const float4*)(src + row*384 + j*16);
            *(float4*)(smem + row*400 + j*16) = v;
        }
        const char* srcb = (const char*)(g_b16 + ((size_t)(bz*NNPTS) + col0)*192);
        #pragma unroll
        for (int i = 0; i < 6; i++) {
            int idx = tid + i*256;               // 0..1535
            int row = idx / 24, j = idx - row*24;
            float4 v = *(const float4*)(srcb + row*384 + j*16);
            *(float4*)(smem + 51200 + row*400 + j*16) = v;
        }
    }
    if (tid < 128) {
        int r = tid;
        #pragma unroll
        for (int d = 0; d < 3; d++) P0[d*128 + r] = pc0[(bz*NNPTS+row0+r)*3 + d];
        N0s[r] = g_n0[bz*NNPTS + row0 + r];
    } else if (tid < 192) {
        int r = tid - 128;
        #pragma unroll
        for (int d = 0; d < 3; d++) P1[d*64 + r] = pc1[(bz*NNPTS+col0+r)*3 + d];
        N1s[r] = g_n1[bz*NNPTS + col0 + r];
    }
    __syncthreads();

    int wr = wid >> 1, wc = wid & 1;
    float acc[2][4][4];
    #pragma unroll
    for (int mi = 0; mi < 2; mi++)
        #pragma unroll
        for (int ni = 0; ni < 4; ni++)
            acc[mi][ni][0]=acc[mi][ni][1]=acc[mi][ni][2]=acc[mi][ni][3]=0.f;

    uint32_t sb = smem_u32(smem);
    uint32_t aOff = (uint32_t)((wr*32 + ((lane>>3)&1)*8 + (lane&7))*400 + (lane>>4)*16);
    uint32_t bOff = 51200u + (uint32_t)((wc*32 + (lane>>4)*8 + (lane&7))*400 + ((lane>>3)&1)*16);

    #pragma unroll 2
    for (int k0 = 0; k0 < 192; k0 += 16) {
        uint32_t a[2][4];
        ldm_x4(a[0], sb + aOff + k0*2);
        ldm_x4(a[1], sb + aOff + 16*400 + k0*2);
        uint32_t bfr[2][4];
        ldm_x4(bfr[0], sb + bOff + k0*2);
        ldm_x4(bfr[1], sb + bOff + 16*400 + k0*2);
        #pragma unroll
        for (int mi = 0; mi < 2; mi++)
            #pragma unroll
            for (int ni = 0; ni < 4; ni++) {
                uint32_t bb[2] = { bfr[ni>>1][(ni&1)*2], bfr[ni>>1][(ni&1)*2 + 1] };
                mma16816(acc[mi][ni], a[mi], bb);
            }
    }
    __syncthreads();                         // done reading A/B; reuse A as D (bf16, stride 144 B)

    {
        float eps = __expf(epsilon[0]) + 0.025f;
        float inv_eps = 1.0f/eps;
        #pragma unroll
        for (int mi = 0; mi < 2; mi++) {
            int rA = wr*32 + mi*16 + g;
            #pragma unroll
            for (int half = 0; half < 2; half++) {
                int r = rA + half*8;
                float p0x = P0[r], p0y = P0[128+r], p0z = P0[256+r];
                float n0v = N0s[r];
                #pragma unroll
                for (int ni = 0; ni < 4; ni++) {
                    int c0 = wc*32 + ni*8 + t*2;
                    float v[2];
                    #pragma unroll
                    for (int cc = 0; cc < 2; cc++) {
                        int c = c0 + cc;
                        float dot = acc[mi][ni][half*2 + cc];
                        float pd  = fmaf(p0x, P1[c], fmaf(p0y, P1[64+c], p0z*P1[128+c]));
                        float sqd = n0v + N1s[c] - 2.0f*pd;
                        v[cc] = (sqd < 100.0f) ? __expf((dot - 1.0f)*inv_eps) : 0.0f;
                    }
                    __nv_bfloat162 pk = __floats2bfloat162_rn(v[0], v[1]);
                    *(uint32_t*)(smem + r*144 + c0*2) = *(uint32_t*)&pk;
                }
            }
        }
    }
    __syncthreads();
    {   // coalesced store of bf16 D tile (128 rows x 128 B)
        #pragma unroll
        for (int it = 0; it < 4; it++) {
            int idx = tid + it*256;              // 1024 uint4 slots
            int row = idx >> 3, j = idx & 7;
            uint4 v = *(const uint4*)(smem + row*144 + j*16);
            *(uint4*)((char*)(g_K16 + ((size_t)(bz*NNPTS) + row0 + row)*NNPTS + col0) + j*16) = v;
        }
    }
    if (tid < 64) {                          // column sums of this tile (bf16-consistent)
        float s = 0.f;
        #pragma unroll 8
        for (int r = 0; r < 128; r++)
            s += __bfloat162float(*(__nv_bfloat16*)(smem + r*144 + tid*2));
        atomicAdd(&g_colsum[bz*NNPTS + col0 + tid], s);
    }
}

// -------- b vector, stored transposed for rowpass ------------------------
__global__ __launch_bounds__(256)
void bvec_kernel(const float* __restrict__ pc1,
                 const float* __restrict__ gamma, const float* __restrict__ epsilon)
{
    int i = blockIdx.x*blockDim.x + threadIdx.x;
    if (i >= NTOT) return;
    float eps = expf(epsilon[0]) + 0.025f;
    float gam = expf(gamma[0]);
    float power = gam/(gam+eps);
    float kta = g_colsum[i] * (1.0f/NNPTS);
    float b = powf((1.0f/NNPTS)/(kta + 1e-8f), power);
    int bz = i / NNPTS, c = i % NNPTS;
    g_w4t[bz*NNPTS + (c & 3)*1024 + (c >> 2)] =
        make_float4(b, b*pc1[i*3+0], b*pc1[i*3+1], b*pc1[i*3+2]);
}

// ---------------- row pass: Kb, K b pc1 -> ot_flow (bf16 K) --------------
__global__ __launch_bounds__(256)
void rowpass_kernel(const float* __restrict__ pc0,
                    const float* __restrict__ gamma, const float* __restrict__ epsilon)
{
    __shared__ float rbuf[8][4][4];
    int tid = threadIdx.x;
    int r0 = blockIdx.x * 4;
    int bz = r0 / NNPTS;
    const float4* wt = g_w4t + bz*NNPTS;
    int wid = tid >> 5, lane = tid & 31;

    const uint2* K0 = (const uint2*)(g_K16 + (size_t)(r0+0)*NNPTS);
    const uint2* K1 = (const uint2*)(g_K16 + (size_t)(r0+1)*NNPTS);
    const uint2* K2 = (const uint2*)(g_K16 + (size_t)(r0+2)*NNPTS);
    const uint2* K3 = (const uint2*)(g_K16 + (size_t)(r0+3)*NNPTS);
    float acc[4][4];
    #pragma unroll
    for (int r = 0; r < 4; r++)
        acc[r][0]=acc[r][1]=acc[r][2]=acc[r][3]=0.f;
    #pragma unroll
    for (int i = 0; i < 4; i++) {
        int f = tid + i*256;
        float4 w0 = __ldg(&wt[f]),      w1 = __ldg(&wt[1024+f]);
        float4 w2 = __ldg(&wt[2048+f]), w3 = __ldg(&wt[3072+f]);
        uint2 kr[4] = { K0[f], K1[f], K2[f], K3[f] };
        #pragma unroll
        for (int r = 0; r < 4; r++) {
            float2 lo = __bfloat1622float2(*(__nv_bfloat162*)&kr[r].x);
            float2 hi = __bfloat1622float2(*(__nv_bfloat162*)&kr[r].y);
            acc[r][0] = fmaf(lo.x,w0.x, fmaf(lo.y,w1.x, fmaf(hi.x,w2.x, fmaf(hi.y,w3.x, acc[r][0]))));
            acc[r][1] = fmaf(lo.x,w0.y, fmaf(lo.y,w1.y, fmaf(hi.x,w2.y, fmaf(hi.y,w3.y, acc[r][1]))));
            acc[r][2] = fmaf(lo.x,w0.z, fmaf(lo.y,w1.z, fmaf(hi.x,w2.z, fmaf(hi.y,w3.z, acc[r][2]))));
            acc[r][3] = fmaf(lo.x,w0.w, fmaf(lo.y,w1.w, fmaf(hi.x,w2.w, fmaf(hi.y,w3.w, acc[r][3]))));
        }
    }
    #pragma unroll
    for (int r = 0; r < 4; r++) {
        #pragma unroll
        for (int o = 16; o > 0; o >>= 1) {
            acc[r][0] += __shfl_xor_sync(0xffffffffu, acc[r][0], o);
            acc[r][1] += __shfl_xor_sync(0xffffffffu, acc[r][1], o);
            acc[r][2] += __shfl_xor_sync(0xffffffffu, acc[r][2], o);
            acc[r][3] += __shfl_xor_sync(0xffffffffu, acc[r][3], o);
        }
        if (lane == 0) {
            rbuf[wid][r][0]=acc[r][0]; rbuf[wid][r][1]=acc[r][1];
            rbuf[wid][r][2]=acc[r][2]; rbuf[wid][r][3]=acc[r][3];
        }
    }
    __syncthreads();
    if (tid < 4) {
        int r = tid;
        float Kb=0.f,Sx=0.f,Sy=0.f,Sz=0.f;
        #pragma unroll
        for (int w = 0; w < 8; w++) {
            Kb += rbuf[w][r][0]; Sx += rbuf[w][r][1];
            Sy += rbuf[w][r][2]; Sz += rbuf[w][r][3];
        }
        float eps = expf(epsilon[0]) + 0.025f;
        float gam = expf(gamma[0]);
        float power = gam/(gam+eps);
        float a  = powf((1.0f/NNPTS)/(Kb + 1e-8f), power);
        float rs = a*Kb;
        float inv = 1.0f/(rs + 1e-8f);
        int row = r0 + r;
        g_otflow[row*3+0] = a*Sx*inv - pc0[row*3+0];
        g_otflow[row*3+1] = a*Sy*inv - pc0[row*3+1];
        g_otflow[row*3+2] = a*Sz*inv - pc0[row*3+2];
    }
}

// ---------------- conv1: edge conv (6->32->32->32) + y2 epilogue ---------
__global__ __launch_bounds__(256)
void conv1_kernel(const float* __restrict__ pc0,
                  const float* __restrict__ W1, const float* __restrict__ B1,
                  const float* __restrict__ W2, const float* __restrict__ B2,
                  const float* __restrict__ W3, const float* __restrict__ B3,
                  const float* __restrict__ W2a)
{
    __shared__ __align__(16) float in_s[8][KNN][8];
    __shared__ __align__(16) float h[8][32];
    __shared__ __align__(16) float h2[8][32];
    __shared__ int   nb_s[8][KNN];

    int tid = threadIdx.x;
    int g = tid >> 5, c = tid & 31;
    int node = blockIdx.x*8 + g;
    int b = node / NNPTS;

    nb_s[g][c] = g_idx[node*KNN + c];
    __syncthreads();

    for (int e = c; e < KNN*6; e += 32) {
        int j = e / 6, k = e % 6;
        int nb = nb_s[g][j];
        float v;
        if (k < 3) v = g_otflow[(b*NNPTS + nb)*3 + k];
        else       v = pc0[(b*NNPTS + nb)*3 + (k-3)] - pc0[node*3 + (k-3)];
        in_s[g][j][k] = v;
    }
    __syncthreads();

    float acc[KNN];
    float bias1 = B1[c];
    #pragma unroll
    for (int j = 0; j < KNN; j++) acc[j] = bias1;
    #pragma unroll
    for (int k = 0; k < 6; k++) {
        float w = W1[k*32 + c];
        #pragma unroll
        for (int j = 0; j < KNN; j++) acc[j] = fmaf(in_s[g][j][k], w, acc[j]);
    }
    float mx = -3.4e38f;
    #pragma unroll
    for (int j = 0; j < KNN; j++) mx = fmaxf(mx, lrelu(acc[j]));
    h[g][c] = mx;
    __syncthreads();

    {
        const float4* hv = (const float4*)h[g];
        float a2 = B2[c], a2b = 0.f;
        #pragma unroll
        for (int k4 = 0; k4 < 8; k4++) {
            float4 x = hv[k4]; int k = k4*4;
            a2  = fmaf(x.x, W2[(k+0)*32 + c], a2);
            a2b = fmaf(x.y, W2[(k+1)*32 + c], a2b);
            a2  = fmaf(x.z, W2[(k+2)*32 + c], a2);
            a2b = fmaf(x.w, W2[(k+3)*32 + c], a2b);
        }
        h2[g][c] = lrelu(a2 + a2b);
    }
    __syncthreads();

    {
        const float4* hv = (const float4*)h2[g];
        float a3 = B3[c], a3b = 0.f;
        #pragma unroll
        for (int k4 = 0; k4 < 8; k4++) {
            float4 x = hv[k4]; int k = k4*4;
            a3  = fmaf(x.x, W3[(k+0)*32 + c], a3);
            a3b = fmaf(x.y, W3[(k+1)*32 + c], a3b);
            a3  = fmaf(x.z, W3[(k+2)*32 + c], a3);
            a3b = fmaf(x.w, W3[(k+3)*32 + c], a3b);
        }
        h[g][c] = lrelu(a3 + a3b);
    }
    __syncthreads();

    #pragma unroll
    for (int t = 0; t < 2; t++) {
        int cc = c + t*32;
        const float4* hv = (const float4*)h[g];
        float y = 0.f, yb = 0.f;
        #pragma unroll
        for (int k4 = 0; k4 < 8; k4++) {
            float4 x = hv[k4]; int k = k4*4;
            y  = fmaf(x.x, W2a[(k+0)*64 + cc], y);
            yb = fmaf(x.y, W2a[(k+1)*64 + cc], yb);
            y  = fmaf(x.z, W2a[(k+2)*64 + cc], y);
            yb = fmaf(x.w, W2a[(k+3)*64 + cc], yb);
        }
        g_y2[(size_t)node*64 + cc] = y + yb;
    }
}

// ---------------- conv2: gather y2 + edge -> 64, dense x2, y3 epi --------
__global__ __launch_bounds__(256)
void conv2_kernel(const float* __restrict__ pc0,
                  const float* __restrict__ W1, const float* __restrict__ B1,
                  const float* __restrict__ W2, const float* __restrict__ B2,
                  const float* __restrict__ W3, const float* __restrict__ B3,
                  const float* __restrict__ W3a)
{
    __shared__ int    nb_s[4][KNN];
    __shared__ float4 es[4][KNN];
    __shared__ __align__(16) float h[4][64];
    __shared__ __align__(16) float h2[4][64];

    int tid = threadIdx.x;
    int g = tid >> 6, c = tid & 63;
    int node = blockIdx.x*4 + g;
    int b = node / NNPTS;

    if (c < KNN) {
        int nb = g_idx[node*KNN + c];
        nb_s[g][c] = nb;
        es[g][c] = make_float4(pc0[(b*NNPTS+nb)*3+0] - pc0[node*3+0],
                               pc0[(b*NNPTS+nb)*3+1] - pc0[node*3+1],
                               pc0[(b*NNPTS+nb)*3+2] - pc0[node*3+2], 0.f);
    }
    __syncthreads();

    const float* yb = g_y2 + (size_t)b*NNPTS*64;
    float yv[KNN];
    #pragma unroll
    for (int j = 0; j < KNN; j++) yv[j] = yb[nb_s[g][j]*64 + c];

    float wb0 = W1[32*64 + c], wb1 = W1[33*64 + c], wb2 = W1[34*64 + c];
    float bias = B1[c];
    float mx = -3.4e38f;
    #pragma unroll
    for (int j = 0; j < KNN; j++) {
        float4 e = es[g][j];
        float a = yv[j] + fmaf(e.x, wb0, fmaf(e.y, wb1, fmaf(e.z, wb2, bias)));
        mx = fmaxf(mx, lrelu(a));
    }
    h[g][c] = mx;
    __syncthreads();

    {
        const float4* hv = (const float4*)h[g];
        float a2 = B2[c], a2b = 0.f;
        #pragma unroll
        for (int k4 = 0; k4 < 16; k4++) {
            float4 x = hv[k4]; int k = k4*4;
            a2  = fmaf(x.x, W2[(k+0)*64 + c], a2);
            a2b = fmaf(x.y, W2[(k+1)*64 + c], a2b);
            a2  = fmaf(x.z, W2[(k+2)*64 + c], a2);
            a2b = fmaf(x.w, W2[(k+3)*64 + c], a2b);
        }
        h2[g][c] = lrelu(a2 + a2b);
    }
    __syncthreads();

    {
        const float4* hv = (const float4*)h2[g];
        float a3 = B3[c], a3b = 0.f;
        #pragma unroll
        for (int k4 = 0; k4 < 16; k4++) {
            float4 x = hv[k4]; int k = k4*4;
            a3  = fmaf(x.x, W3[(k+0)*64 + c], a3);
            a3b = fmaf(x.y, W3[(k+1)*64 + c], a3b);
            a3  = fmaf(x.z, W3[(k+2)*64 + c], a3);
            a3b = fmaf(x.w, W3[(k+3)*64 + c], a3b);
        }
        h[g][c] = lrelu(a3 + a3b);
    }
    __syncthreads();

    #pragma unroll
    for (int t = 0; t < 2; t++) {
        int cc = c + t*64;
        const float4* hv = (const float4*)h[g];
        float y = 0.f, ybb = 0.f;
        #pragma unroll
        for (int k4 = 0; k4 < 16; k4++) {
            float4 x = hv[k4]; int k = k4*4;
            y   = fmaf(x.x, W3a[(k+0)*128 + cc], y);
            ybb = fmaf(x.y, W3a[(k+1)*128 + cc], ybb);
            y   = fmaf(x.z, W3a[(k+2)*128 + cc], y);
            ybb = fmaf(x.w, W3a[(k+3)*128 + cc], ybb);
        }
        g_y3[(size_t)node*128 + cc] = y + ybb;
    }
}

// ---------------- conv3: gather y3 + edge -> 128, dense, fc, residual ----
__global__ __launch_bounds__(256)
void conv3_kernel(const float* __restrict__ pc0,
                  const float* __restrict__ W1, const float* __restrict__ B1,
                  const float* __restrict__ W2, const float* __restrict__ B2,
                  const float* __restrict__ W3, const float* __restrict__ B3,
                  const float* __restrict__ Wfc, const float* __restrict__ Bfc,
                  float* __restrict__ dout)
{
    __shared__ int    nb_s[2][KNN];
    __shared__ float4 es[2][KNN];
    __shared__ __align__(16) float h[2][128];
    __shared__ __align__(16) float h2[2][128];

    int tid = threadIdx.x;
    int g = tid >> 7, c = tid & 127;
    int node = blockIdx.x*2 + g;
    int b = node / NNPTS;

    if (c < KNN) {
        int nb = g_idx[node*KNN + c];
        nb_s[g][c] = nb;
        es[g][c] = make_float4(pc0[(b*NNPTS+nb)*3+0] - pc0[node*3+0],
                               pc0[(b*NNPTS+nb)*3+1] - pc0[node*3+1],
                               pc0[(b*NNPTS+nb)*3+2] - pc0[node*3+2], 0.f);
    }
    __syncthreads();

    const float* yb = g_y3 + (size_t)b*NNPTS*128;
    float yv[KNN];
    #pragma unroll
    for (int j = 0; j < KNN; j++) yv[j] = yb[nb_s[g][j]*128 + c];

    float wb0 = W1[64*128 + c], wb1 = W1[65*128 + c], wb2 = W1[66*128 + c];
    float bias = B1[c];
    float mx = -3.4e38f;
    #pragma unroll
    for (int j = 0; j < KNN; j++) {
        float4 e = es[g][j];
        float a = yv[j] + fmaf(e.x, wb0, fmaf(e.y, wb1, fmaf(e.z, wb2, bias)));
        mx = fmaxf(mx, lrelu(a));
    }
    h[g][c] = mx;
    __syncthreads();

    {
        const float4* hv = (const float4*)h[g];
        float a2 = B2[c], a2b = 0.f;
        #pragma unroll
        for (int k4 = 0; k4 < 32; k4++) {
            float4 x = hv[k4]; int k = k4*4;
            a2  = fmaf(x.x, W2[(k+0)*128 + c], a2);
            a2b = fmaf(x.y, W2[(k+1)*128 + c], a2b);
            a2  = fmaf(x.z, W2[(k+2)*128 + c], a2);
            a2b = fmaf(x.w, W2[(k+3)*128 + c], a2b);
        }
        h2[g][c] = lrelu(a2 + a2b);
    }
    __syncthreads();

    {
        const float4* hv = (const float4*)h2[g];
        float a3 = B3[c], a3b = 0.f;
        #pragma unroll
        for (int k4 = 0; k4 < 32; k4++) {
            float4 x = hv[k4]; int k = k4*4;
            a3  = fmaf(x.x, W3[(k+0)*128 + c], a3);
            a3b = fmaf(x.y, W3[(k+1)*128 + c], a3b);
            a3  = fmaf(x.z, W3[(k+2)*128 + c], a3);
            a3b = fmaf(x.w, W3[(k+3)*128 + c], a3b);
        }
        h[g][c] = lrelu(a3 + a3b);
    }
    __syncthreads();

    if (c < 3) {
        float o = Bfc[c];
        for (int k = 0; k < 128; k++) o = fmaf(h[g][k], Wfc[k*3 + c], o);
        dout[node*3 + c] = g_otflow[node*3 + c] + o;
    }
}

// ---------------- launch --------------------------------------------------
extern "C" void kernel_launch(void* const* d_in, const int* in_sizes, int n_in,
                              void* d_out, int out_size)
{
    const float* pc0   = (const float*)d_in[0];
    const float* pc1   = (const float*)d_in[1];
    const float* f0    = (const float*)d_in[2];
    const float* f1    = (const float*)d_in[3];
    const float* gamma = (const float*)d_in[4];
    const float* eps   = (const float*)d_in[5];
    const float* w1_1=(const float*)d_in[6],  *b1_1=(const float*)d_in[7];
    const float* w1_2=(const float*)d_in[8],  *b1_2=(const float*)d_in[9];
    const float* w1_3=(const float*)d_in[10], *b1_3=(const float*)d_in[11];
    const float* w2_1=(const float*)d_in[12], *b2_1=(const float*)d_in[13];
    const float* w2_2=(const float*)d_in[14], *b2_2=(const float*)d_in[15];
    const float* w2_3=(const float*)d_in[16], *b2_3=(const float*)d_in[17];
    const float* w3_1=(const float*)d_in[18], *b3_1=(const float*)d_in[19];
    const float* w3_2=(const float*)d_in[20], *b3_2=(const float*)d_in[21];
    const float* w3_3=(const float*)d_in[22], *b3_3=(const float*)d_in[23];
    const float* wfc =(const float*)d_in[24], *bfc =(const float*)d_in[25];
    float* out = (float*)d_out;

    cudaFuncSetAttribute(kmat_kernel, cudaFuncAttributeMaxDynamicSharedMemorySize, 80896);

    prep_norm_kernel<<<(2*NTOT + 255)/256, 256>>>(pc0, pc1);      // 1
    knn_kernel<<<NTOT, 256>>>();                                   // 2
    prep_feat_kernel<<<2048, 256>>>(f0, f1);                       // 3
    kmat_kernel<<<dim3(NNPTS/64, NNPTS/128, BB), 256, 79872>>>(pc0, pc1, eps); // 4 = ncu slot
    bvec_kernel<<<(NTOT + 255)/256, 256>>>(pc1, gamma, eps);
    rowpass_kernel<<<NTOT/4, 256>>>(pc0, gamma, eps);
    conv1_kernel<<<NTOT/8, 256>>>(pc0, w1_1,b1_1, w1_2,b1_2, w1_3,b1_3, w2_1);
    conv2_kernel<<<NTOT/4, 256>>>(pc0, w2_1,b2_1, w2_2,b2_2, w2_3,b2_3, w3_1);
    conv3_kernel<<<NTOT/2, 256>>>(pc0, w3_1,b3_1, w3_2,b3_2, w3_3,b3_3, wfc,bfc, out);
}